// round 5
// baseline (speedup 1.0000x reference)
#include <cuda_runtime.h>
#include <math.h>

#define BDIM 8
#define FDIM 1025
#define MDIM 8
#define TDIM 512
#define NBF (BDIM * FDIM)            // 8200
#define NTHREADS 288
#define XS 516                        // padded SMEM row stride (16B-aligned rows)

#define QELEMS (NBF * MDIM * MDIM)           // 524,800  (Q stored as real part only)
#define XTCOUNT (NBF * MDIM * TDIM)          // 33,587,200
#define PER_B_XT (FDIM * MDIM * TDIM)        // 4,198,400
#define PER_B_QE (FDIM * MDIM * MDIM)        // 65,600
#define TOTAL4 ((QELEMS + XTCOUNT) / 4)      // 8,528,000 float4s
#define Q4 (QELEMS / 4)                      // 131,200

// SMEM layout (float offsets)
#define OFF_SXR 0
#define OFF_SXI (OFF_SXR + MDIM * XS)        // 4128
#define OFF_SR  (OFF_SXI + MDIM * XS)        // 8256
#define OFF_V   (OFF_SR + MDIM * XS)         // 12384  (512 float2)
#define OFF_PART (OFF_V + 1024)              // 13408  (2304 float2)
#define OFF_SQ  (OFF_PART + 4608)            // 18016  (64 float2)
#define OFF_RED (OFF_SQ + 128)               // 18144  (288 float)
#define SMEM_FLOATS (OFF_RED + NTHREADS)
#define SMEM_BYTES (SMEM_FLOATS * 4)

typedef unsigned long long ull;
#define SGN2 0x8000000080000000ULL

__device__ __forceinline__ ull f2_pack(float lo, float hi) {
    ull r; asm("mov.b64 %0,{%1,%2};" : "=l"(r) : "f"(lo), "f"(hi)); return r;
}
__device__ __forceinline__ void f2_unpack(ull v, float& lo, float& hi) {
    asm("mov.b64 {%0,%1},%2;" : "=f"(lo), "=f"(hi) : "l"(v));
}
__device__ __forceinline__ ull f2_fma(ull a, ull b, ull c) {
    ull d; asm("fma.rn.f32x2 %0,%1,%2,%3;" : "=l"(d) : "l"(a), "l"(b), "l"(c)); return d;
}
__device__ __forceinline__ ull f2_mul(ull a, ull b) {
    ull d; asm("mul.rn.f32x2 %0,%1,%2;" : "=l"(d) : "l"(a), "l"(b)); return d;
}

__device__ float g_partial[NBF];
__device__ float g_xtscale[BDIM];
__device__ float g_qscale[BDIM];

__constant__ unsigned char c_pm[36] = {
    0,0,0,0,0,0,0,0,
    1,1,1,1,1,1,1,
    2,2,2,2,2,2,
    3,3,3,3,3,
    4,4,4,4,
    5,5,5,
    6,6,
    7};
__constant__ unsigned char c_pn[36] = {
    0,1,2,3,4,5,6,7,
    1,2,3,4,5,6,7,
    2,3,4,5,6,7,
    3,4,5,6,7,
    4,5,6,7,
    5,6,7,
    6,7,
    7};

__global__ __launch_bounds__(NTHREADS)
void iss_main(const float* __restrict__ r,
              const float* __restrict__ Qr,
              const float* __restrict__ Qi,
              const float* __restrict__ xr,
              const float* __restrict__ xi,
              float* __restrict__ out)
{
    extern __shared__ float sm[];
    float*  sxr  = sm + OFF_SXR;
    float*  sxi  = sm + OFF_SXI;
    float*  sr   = sm + OFF_SR;
    float2* V    = (float2*)(sm + OFF_V);     // [k][m][n]
    float2* part = (float2*)(sm + OFF_PART);  // [pair][k][chunk]
    float2* sQ   = (float2*)(sm + OFF_SQ);    // [k][m]
    float*  red  = sm + OFF_RED;

    const int tid = threadIdx.x;
    const int bf = blockIdx.x;
    const size_t base = (size_t)bf * (MDIM * TDIM);

    // ---- stage inputs in SMEM via float4 (r clipped at load) ----
    {
        const float4* xr4 = (const float4*)(xr + base);
        const float4* xi4 = (const float4*)(xi + base);
        const float4* r4  = (const float4*)(r + base);
        for (int i = tid; i < MDIM * TDIM / 4; i += NTHREADS) {
            int m = i >> 7, t4 = (i & 127) << 2;
            float4 a = xr4[i];
            *(float4*)(sxr + m * XS + t4) = a;
            float4 b = xi4[i];
            *(float4*)(sxi + m * XS + t4) = b;
            float4 c = r4[i];
            c.x = fmaxf(c.x, 1e-3f); c.y = fmaxf(c.y, 1e-3f);
            c.z = fmaxf(c.z, 1e-3f); c.w = fmaxf(c.w, 1e-3f);
            *(float4*)(sr + m * XS + t4) = c;
        }
    }
    if (tid < 64) {
        sQ[tid] = make_float2(Qr[(size_t)bf * 64 + tid], Qi[(size_t)bf * 64 + tid]);
    }
    __syncthreads();

    // ---- V[k,m,n] = (1/T) sum_t clip(r)[k,t] * x[m,t] * conj(x[n,t]) ----
    {
        int chunk = tid / 36;
        int pair  = tid - chunk * 36;
        int m = c_pm[pair], n = c_pn[pair];
        const ulonglong2* pxrm = (const ulonglong2*)(sxr + m * XS + chunk * 64);
        const ulonglong2* pxim = (const ulonglong2*)(sxi + m * XS + chunk * 64);
        const ulonglong2* pxrn = (const ulonglong2*)(sxr + n * XS + chunk * 64);
        const ulonglong2* pxin = (const ulonglong2*)(sxi + n * XS + chunk * 64);
        const float* srl = sr + chunk * 64;

        ull accx[8], accy[8];
        #pragma unroll
        for (int k = 0; k < 8; k++) { accx[k] = 0ULL; accy[k] = 0ULL; }

        #pragma unroll 2
        for (int q = 0; q < 16; q++) {            // q indexes groups of 4 t's
            ulonglong2 vrm = pxrm[q];
            ulonglong2 vim = pxim[q];
            ulonglong2 vrn = pxrn[q];
            ulonglong2 vin = pxin[q];
            ull a01 = f2_fma(vrm.x, vrn.x, f2_mul(vim.x, vin.x));
            ull a23 = f2_fma(vrm.y, vrn.y, f2_mul(vim.y, vin.y));
            ull b01 = f2_fma(vim.x, vrn.x, f2_mul(vrm.x ^ SGN2, vin.x));
            ull b23 = f2_fma(vim.y, vrn.y, f2_mul(vrm.y ^ SGN2, vin.y));
            #pragma unroll
            for (int k = 0; k < 8; k++) {
                ulonglong2 rk = *(const ulonglong2*)(srl + k * XS + q * 4);
                accx[k] = f2_fma(rk.x, a01, accx[k]);
                accx[k] = f2_fma(rk.y, a23, accx[k]);
                accy[k] = f2_fma(rk.x, b01, accy[k]);
                accy[k] = f2_fma(rk.y, b23, accy[k]);
            }
        }
        #pragma unroll
        for (int k = 0; k < 8; k++) {
            float xl, xh, yl, yh;
            f2_unpack(accx[k], xl, xh);
            f2_unpack(accy[k], yl, yh);
            part[(pair * 8 + k) * 8 + chunk] = make_float2(xl + xh, yl + yh);
        }
    }
    __syncthreads();

    // reduce over chunks, Hermitian fill. 36*8 = 288 items exactly.
    {
        int pair = tid >> 3, k = tid & 7;
        int m = c_pm[pair], n = c_pn[pair];
        float2 s = make_float2(0.f, 0.f);
        #pragma unroll
        for (int c = 0; c < 8; c++) {
            float2 p = part[(pair * 8 + k) * 8 + c];
            s.x += p.x; s.y += p.y;
        }
        s.x *= (1.0f / TDIM);
        s.y *= (1.0f / TDIM);
        V[(k * 8 + m) * 8 + n] = s;
        V[(k * 8 + n) * 8 + m] = make_float2(s.x, -s.y);
    }
    __syncthreads();

    // trV + diagonal regularization
    if (tid < 8) {
        int k = tid;
        float tr = 0.f;
        #pragma unroll
        for (int m = 0; m < 8; m++) tr += V[(k * 8 + m) * 8 + m].x;
        float reg = fmaxf(tr, 1.0f) * 1e-6f;
        #pragma unroll
        for (int m = 0; m < 8; m++) V[(k * 8 + m) * 8 + m].x += reg;
    }
    __syncthreads();

    // ---- 2 x 8 sweep, fully register-resident on warp 0 ----
    // lane l owns kp = l>>2, rows m0 = 2*(l&3), m1 = m0+1 of Q and V[kp].
    if (tid < 32) {
        const int lane = tid;
        const int kp = lane >> 2;
        const int j  = lane & 3;
        const int m0 = 2 * j, m1 = 2 * j + 1;

        float2 Vr0[8], Vr1[8];
        #pragma unroll
        for (int n = 0; n < 8; n++) {
            Vr0[n] = V[(kp * 8 + m0) * 8 + n];
            Vr1[n] = V[(kp * 8 + m1) * 8 + n];
        }
        float2 Q0 = sQ[kp * 8 + m0];
        float2 Q1 = sQ[kp * 8 + m1];

        #pragma unroll 1
        for (int it = 0; it < 2; it++) {
            #pragma unroll 1
            for (int k = 0; k < 8; k++) {
                // broadcast q = current row k of Q from its 4 owner lanes
                float qr[8], qi[8];
                #pragma unroll
                for (int jp = 0; jp < 4; jp++) {
                    int src = k * 4 + jp;
                    qr[2 * jp]     = __shfl_sync(0xffffffffu, Q0.x, src);
                    qi[2 * jp]     = __shfl_sync(0xffffffffu, Q0.y, src);
                    qr[2 * jp + 1] = __shfl_sync(0xffffffffu, Q1.x, src);
                    qi[2 * jp + 1] = __shfl_sync(0xffffffffu, Q1.y, src);
                }
                // Vq[kp,m] = sum_n V[kp,m,n] * conj(q_n)
                float vq0r = 0.f, vq0i = 0.f, vq1r = 0.f, vq1i = 0.f;
                #pragma unroll
                for (int n = 0; n < 8; n++) {
                    vq0r += Vr0[n].x * qr[n] + Vr0[n].y * qi[n];
                    vq0i += Vr0[n].y * qr[n] - Vr0[n].x * qi[n];
                    vq1r += Vr1[n].x * qr[n] + Vr1[n].y * qi[n];
                    vq1i += Vr1[n].y * qr[n] - Vr1[n].x * qi[n];
                }
                // partial qVq = Re(q_m * Vq_m), partial num = Q[kp,m] * Vq_m
                float pq  = qr[m0] * vq0r - qi[m0] * vq0i
                          + qr[m1] * vq1r - qi[m1] * vq1i;
                float pnr = Q0.x * vq0r - Q0.y * vq0i
                          + Q1.x * vq1r - Q1.y * vq1i;
                float pni = Q0.x * vq0i + Q0.y * vq0r
                          + Q1.x * vq1i + Q1.y * vq1r;
                // reduce over the 4 lanes sharing this kp
                pq  += __shfl_xor_sync(0xffffffffu, pq, 1);
                pnr += __shfl_xor_sync(0xffffffffu, pnr, 1);
                pni += __shfl_xor_sync(0xffffffffu, pni, 1);
                pq  += __shfl_xor_sync(0xffffffffu, pq, 2);
                pnr += __shfl_xor_sync(0xffffffffu, pnr, 2);
                pni += __shfl_xor_sync(0xffffffffu, pni, 2);

                float qv = fmaxf(pq, 1e-6f);
                float vrr, vii;
                if (kp == k) {
                    vrr = 1.0f - 1.0f / sqrtf(qv);
                    vii = 0.0f;
                } else {
                    vrr = pnr / qv;
                    vii = pni / qv;
                }
                // Q[kp,m] -= v * q_m
                Q0.x -= vrr * qr[m0] - vii * qi[m0];
                Q0.y -= vrr * qi[m0] + vii * qr[m0];
                Q1.x -= vrr * qr[m1] - vii * qi[m1];
                Q1.y -= vrr * qi[m1] + vii * qr[m1];
            }
        }
        sQ[kp * 8 + m0] = Q0;
        sQ[kp * 8 + m1] = Q1;
    }
    __syncthreads();

    // ---- Qx = Q @ x ; xt = |Qx|^2 (unnormalized); local sum for scale ----
    float local = 0.f;
    float* out_xt = out + QELEMS + base;
    if (tid < 256) {
        int m = tid >> 5;
        int lane = tid & 31;
        ull Qxx2[8], Qyy2[8];
        #pragma unroll
        for (int n = 0; n < 8; n++) {
            float2 Qv = sQ[m * 8 + n];
            Qxx2[n] = f2_pack(Qv.x, Qv.x);
            Qyy2[n] = f2_pack(Qv.y, Qv.y);
        }
        #pragma unroll
        for (int j = 0; j < 4; j++) {
            int t = (lane + j * 32) * 4;    // 4 consecutive t's
            ull arA01 = 0, arA23 = 0;       // sum Qx*xr
            ull arB01 = 0, arB23 = 0;       // sum Qy*xi  (subtract at end)
            ull ai01 = 0, ai23 = 0;         // sum Qx*xi + Qy*xr
            #pragma unroll
            for (int n = 0; n < 8; n++) {
                ulonglong2 vr = *(const ulonglong2*)(sxr + n * XS + t);
                ulonglong2 vi = *(const ulonglong2*)(sxi + n * XS + t);
                arA01 = f2_fma(Qxx2[n], vr.x, arA01);
                arA23 = f2_fma(Qxx2[n], vr.y, arA23);
                arB01 = f2_fma(Qyy2[n], vi.x, arB01);
                arB23 = f2_fma(Qyy2[n], vi.y, arB23);
                ai01  = f2_fma(Qxx2[n], vi.x, ai01);
                ai23  = f2_fma(Qxx2[n], vi.y, ai23);
                ai01  = f2_fma(Qyy2[n], vr.x, ai01);
                ai23  = f2_fma(Qyy2[n], vr.y, ai23);
            }
            float a0,a1,a2,a3, b0,b1,b2,b3, i0,i1,i2,i3;
            f2_unpack(arA01, a0, a1); f2_unpack(arA23, a2, a3);
            f2_unpack(arB01, b0, b1); f2_unpack(arB23, b2, b3);
            f2_unpack(ai01,  i0, i1); f2_unpack(ai23,  i2, i3);
            float r0 = a0 - b0, r1 = a1 - b1, r2 = a2 - b2, r3 = a3 - b3;
            float4 v;
            v.x = r0 * r0 + i0 * i0;
            v.y = r1 * r1 + i1 * i1;
            v.z = r2 * r2 + i2 * i2;
            v.w = r3 * r3 + i3 * i3;
            local += v.x + v.y + v.z + v.w;
            *(float4*)(out_xt + m * TDIM + t) = v;
        }
    }
    // write unnormalized Q (real part only — output buffer is float32)
    if (tid < 64) {
        out[(size_t)bf * 64 + tid] = sQ[tid].x;
    }
    // deterministic fixed-order block reduction of `local`
    red[tid] = local;
    __syncthreads();
    for (int s = 144; s >= 9; s >>= 1) {
        if (tid < s) red[tid] += red[tid + s];
        __syncthreads();
    }
    if (tid == 0) {
        float s = 0.f;
        #pragma unroll
        for (int i = 0; i < 9; i++) s += red[i];
        g_partial[bf] = s;
    }
}

__global__ void iss_reduce()
{
    __shared__ float red[256];
    int b = blockIdx.x, tid = threadIdx.x;
    float s = 0.f;
    for (int i = tid; i < FDIM; i += 256) s += g_partial[b * FDIM + i];
    red[tid] = s;
    __syncthreads();
    for (int st = 128; st > 0; st >>= 1) {
        if (tid < st) red[tid] += red[tid + st];
        __syncthreads();
    }
    if (tid == 0) {
        float scale = red[0] / (float)PER_B_XT;
        g_xtscale[b] = 1.0f / scale;
        g_qscale[b]  = 1.0f / sqrtf(fmaxf(scale, 1e-6f));
    }
}

// single normalization pass over the whole output buffer (float4)
__global__ void iss_norm(float4* __restrict__ outv)
{
    size_t idx = (size_t)blockIdx.x * blockDim.x + threadIdx.x;
    if (idx >= (size_t)TOTAL4) return;
    float s;
    if (idx < (size_t)Q4) {
        s = g_qscale[(int)(idx / (PER_B_QE / 4))];
    } else {
        s = g_xtscale[(int)((idx - Q4) / (PER_B_XT / 4))];
    }
    float4 v = outv[idx];
    v.x *= s; v.y *= s; v.z *= s; v.w *= s;
    outv[idx] = v;
}

extern "C" void kernel_launch(void* const* d_in, const int* in_sizes, int n_in,
                              void* d_out, int out_size)
{
    const float* r  = (const float*)d_in[0];
    const float* Qr = (const float*)d_in[1];
    const float* Qi = (const float*)d_in[2];
    const float* xr = (const float*)d_in[3];
    const float* xi = (const float*)d_in[4];
    float* out = (float*)d_out;

    cudaFuncSetAttribute(iss_main, cudaFuncAttributeMaxDynamicSharedMemorySize, SMEM_BYTES);

    iss_main<<<NBF, NTHREADS, SMEM_BYTES>>>(r, Qr, Qi, xr, xi, out);
    iss_reduce<<<BDIM, 256>>>();
    iss_norm<<<(TOTAL4 + 255) / 256, 256>>>((float4*)out);
}

// round 6
// speedup vs baseline: 1.1184x; 1.1184x over previous
#include <cuda_runtime.h>
#include <math.h>

#define BDIM 8
#define FDIM 1025
#define MDIM 8
#define TDIM 512
#define NBF (BDIM * FDIM)            // 8200
#define NTHREADS 288
#define XS 516                        // padded SMEM row stride (16B-aligned rows)

#define QELEMS (NBF * MDIM * MDIM)           // 524,800  (Q stored as real part only)
#define XTCOUNT (NBF * MDIM * TDIM)          // 33,587,200
#define PER_B_XT (FDIM * MDIM * TDIM)        // 4,198,400
#define PER_B_QE (FDIM * MDIM * MDIM)        // 65,600
#define TOTAL4 ((QELEMS + XTCOUNT) / 4)      // 8,528,000 float4s
#define Q4 (QELEMS / 4)                      // 131,200

// SMEM layout (float offsets)
#define OFF_SXR 0
#define OFF_SXI (OFF_SXR + MDIM * XS)        // 4128
#define OFF_SR  (OFF_SXI + MDIM * XS)        // 8256
#define OFF_V   (OFF_SR + MDIM * XS)         // 12384  (512 float2)
#define OFF_PART (OFF_V + 1024)              // 13408  (2304 float2)
#define OFF_SQ  (OFF_PART + 4608)            // 18016  (64 float2)
#define OFF_RED (OFF_SQ + 128)               // 18144  (288 float)
#define SMEM_FLOATS (OFF_RED + NTHREADS)
#define SMEM_BYTES (SMEM_FLOATS * 4)

typedef unsigned long long ull;
#define SGN2 0x8000000080000000ULL

__device__ __forceinline__ ull f2_pack(float lo, float hi) {
    ull r; asm("mov.b64 %0,{%1,%2};" : "=l"(r) : "f"(lo), "f"(hi)); return r;
}
__device__ __forceinline__ void f2_unpack(ull v, float& lo, float& hi) {
    asm("mov.b64 {%0,%1},%2;" : "=f"(lo), "=f"(hi) : "l"(v));
}
__device__ __forceinline__ ull f2_fma(ull a, ull b, ull c) {
    ull d; asm("fma.rn.f32x2 %0,%1,%2,%3;" : "=l"(d) : "l"(a), "l"(b), "l"(c)); return d;
}
__device__ __forceinline__ ull f2_mul(ull a, ull b) {
    ull d; asm("mul.rn.f32x2 %0,%1,%2;" : "=l"(d) : "l"(a), "l"(b)); return d;
}

__device__ float g_partial[NBF];
__device__ float g_xtscale[BDIM];
__device__ float g_qscale[BDIM];

__constant__ unsigned char c_pm[36] = {
    0,0,0,0,0,0,0,0,
    1,1,1,1,1,1,1,
    2,2,2,2,2,2,
    3,3,3,3,3,
    4,4,4,4,
    5,5,5,
    6,6,
    7};
__constant__ unsigned char c_pn[36] = {
    0,1,2,3,4,5,6,7,
    1,2,3,4,5,6,7,
    2,3,4,5,6,7,
    3,4,5,6,7,
    4,5,6,7,
    5,6,7,
    6,7,
    7};

__global__ __launch_bounds__(NTHREADS, 3)
void iss_main(const float* __restrict__ r,
              const float* __restrict__ Qr,
              const float* __restrict__ Qi,
              const float* __restrict__ xr,
              const float* __restrict__ xi,
              float* __restrict__ out)
{
    extern __shared__ float sm[];
    float*  sxr  = sm + OFF_SXR;
    float*  sxi  = sm + OFF_SXI;
    float*  sr   = sm + OFF_SR;
    float2* V    = (float2*)(sm + OFF_V);     // [k][m][n]
    float2* part = (float2*)(sm + OFF_PART);  // [pair][k][chunk]
    float2* sQ   = (float2*)(sm + OFF_SQ);    // [k][m]
    float*  red  = sm + OFF_RED;

    const int tid = threadIdx.x;
    const int bf = blockIdx.x;
    const size_t base = (size_t)bf * (MDIM * TDIM);

    // ---- stage inputs in SMEM via float4 (r clipped at load) ----
    {
        const float4* xr4 = (const float4*)(xr + base);
        const float4* xi4 = (const float4*)(xi + base);
        const float4* r4  = (const float4*)(r + base);
        for (int i = tid; i < MDIM * TDIM / 4; i += NTHREADS) {
            int m = i >> 7, t4 = (i & 127) << 2;
            float4 a = xr4[i];
            *(float4*)(sxr + m * XS + t4) = a;
            float4 b = xi4[i];
            *(float4*)(sxi + m * XS + t4) = b;
            float4 c = r4[i];
            c.x = fmaxf(c.x, 1e-3f); c.y = fmaxf(c.y, 1e-3f);
            c.z = fmaxf(c.z, 1e-3f); c.w = fmaxf(c.w, 1e-3f);
            *(float4*)(sr + m * XS + t4) = c;
        }
    }
    if (tid < 64) {
        sQ[tid] = make_float2(Qr[(size_t)bf * 64 + tid], Qi[(size_t)bf * 64 + tid]);
    }
    __syncthreads();

    // ---- V[k,m,n] = (1/T) sum_t clip(r)[k,t] * x[m,t] * conj(x[n,t]) ----
    {
        int chunk = tid / 36;
        int pair  = tid - chunk * 36;
        int m = c_pm[pair], n = c_pn[pair];
        const ulonglong2* pxrm = (const ulonglong2*)(sxr + m * XS + chunk * 64);
        const ulonglong2* pxim = (const ulonglong2*)(sxi + m * XS + chunk * 64);
        const ulonglong2* pxrn = (const ulonglong2*)(sxr + n * XS + chunk * 64);
        const ulonglong2* pxin = (const ulonglong2*)(sxi + n * XS + chunk * 64);
        const float* srl = sr + chunk * 64;

        ull accx[8], accy[8];
        #pragma unroll
        for (int k = 0; k < 8; k++) { accx[k] = 0ULL; accy[k] = 0ULL; }

        #pragma unroll 2
        for (int q = 0; q < 16; q++) {            // q indexes groups of 4 t's
            ulonglong2 vrm = pxrm[q];
            ulonglong2 vim = pxim[q];
            ulonglong2 vrn = pxrn[q];
            ulonglong2 vin = pxin[q];
            ull a01 = f2_fma(vrm.x, vrn.x, f2_mul(vim.x, vin.x));
            ull a23 = f2_fma(vrm.y, vrn.y, f2_mul(vim.y, vin.y));
            ull b01 = f2_fma(vim.x, vrn.x, f2_mul(vrm.x ^ SGN2, vin.x));
            ull b23 = f2_fma(vim.y, vrn.y, f2_mul(vrm.y ^ SGN2, vin.y));
            #pragma unroll
            for (int k = 0; k < 8; k++) {
                ulonglong2 rk = *(const ulonglong2*)(srl + k * XS + q * 4);
                accx[k] = f2_fma(rk.x, a01, accx[k]);
                accx[k] = f2_fma(rk.y, a23, accx[k]);
                accy[k] = f2_fma(rk.x, b01, accy[k]);
                accy[k] = f2_fma(rk.y, b23, accy[k]);
            }
        }
        #pragma unroll
        for (int k = 0; k < 8; k++) {
            float xl, xh, yl, yh;
            f2_unpack(accx[k], xl, xh);
            f2_unpack(accy[k], yl, yh);
            part[(pair * 8 + k) * 8 + chunk] = make_float2(xl + xh, yl + yh);
        }
    }
    __syncthreads();

    // reduce over chunks, Hermitian fill. 36*8 = 288 items exactly.
    {
        int pair = tid >> 3, k = tid & 7;
        int m = c_pm[pair], n = c_pn[pair];
        float2 s = make_float2(0.f, 0.f);
        #pragma unroll
        for (int c = 0; c < 8; c++) {
            float2 p = part[(pair * 8 + k) * 8 + c];
            s.x += p.x; s.y += p.y;
        }
        s.x *= (1.0f / TDIM);
        s.y *= (1.0f / TDIM);
        V[(k * 8 + m) * 8 + n] = s;
        V[(k * 8 + n) * 8 + m] = make_float2(s.x, -s.y);
    }
    __syncthreads();

    // trV + diagonal regularization
    if (tid < 8) {
        int k = tid;
        float tr = 0.f;
        #pragma unroll
        for (int m = 0; m < 8; m++) tr += V[(k * 8 + m) * 8 + m].x;
        float reg = fmaxf(tr, 1.0f) * 1e-6f;
        #pragma unroll
        for (int m = 0; m < 8; m++) V[(k * 8 + m) * 8 + m].x += reg;
    }
    __syncthreads();

    // ---- 2 x 8 sweep, fully register-resident on warp 0 ----
    // lane l owns kp = l>>2, rows m0 = 2*(l&3), m1 = m0+1 of Q and V[kp].
    if (tid < 32) {
        const int lane = tid;
        const int kp = lane >> 2;
        const int j  = lane & 3;
        const int m0 = 2 * j, m1 = 2 * j + 1;

        float2 Vr0[8], Vr1[8];
        #pragma unroll
        for (int n = 0; n < 8; n++) {
            Vr0[n] = V[(kp * 8 + m0) * 8 + n];
            Vr1[n] = V[(kp * 8 + m1) * 8 + n];
        }
        float2 Q0 = sQ[kp * 8 + m0];
        float2 Q1 = sQ[kp * 8 + m1];

        #pragma unroll 1
        for (int it = 0; it < 2; it++) {
            #pragma unroll 1
            for (int k = 0; k < 8; k++) {
                // broadcast q = current row k of Q from its 4 owner lanes
                float qr[8], qi[8];
                #pragma unroll
                for (int jp = 0; jp < 4; jp++) {
                    int src = k * 4 + jp;
                    qr[2 * jp]     = __shfl_sync(0xffffffffu, Q0.x, src);
                    qi[2 * jp]     = __shfl_sync(0xffffffffu, Q0.y, src);
                    qr[2 * jp + 1] = __shfl_sync(0xffffffffu, Q1.x, src);
                    qi[2 * jp + 1] = __shfl_sync(0xffffffffu, Q1.y, src);
                }
                // Vq[kp,m] = sum_n V[kp,m,n] * conj(q_n)
                float vq0r = 0.f, vq0i = 0.f, vq1r = 0.f, vq1i = 0.f;
                #pragma unroll
                for (int n = 0; n < 8; n++) {
                    vq0r += Vr0[n].x * qr[n] + Vr0[n].y * qi[n];
                    vq0i += Vr0[n].y * qr[n] - Vr0[n].x * qi[n];
                    vq1r += Vr1[n].x * qr[n] + Vr1[n].y * qi[n];
                    vq1i += Vr1[n].y * qr[n] - Vr1[n].x * qi[n];
                }
                // partial qVq = Re(q_m * Vq_m), partial num = Q[kp,m] * Vq_m
                float pq  = qr[m0] * vq0r - qi[m0] * vq0i
                          + qr[m1] * vq1r - qi[m1] * vq1i;
                float pnr = Q0.x * vq0r - Q0.y * vq0i
                          + Q1.x * vq1r - Q1.y * vq1i;
                float pni = Q0.x * vq0i + Q0.y * vq0r
                          + Q1.x * vq1i + Q1.y * vq1r;
                // reduce over the 4 lanes sharing this kp
                pq  += __shfl_xor_sync(0xffffffffu, pq, 1);
                pnr += __shfl_xor_sync(0xffffffffu, pnr, 1);
                pni += __shfl_xor_sync(0xffffffffu, pni, 1);
                pq  += __shfl_xor_sync(0xffffffffu, pq, 2);
                pnr += __shfl_xor_sync(0xffffffffu, pnr, 2);
                pni += __shfl_xor_sync(0xffffffffu, pni, 2);

                float qv = fmaxf(pq, 1e-6f);
                float vrr, vii;
                if (kp == k) {
                    vrr = 1.0f - 1.0f / sqrtf(qv);
                    vii = 0.0f;
                } else {
                    vrr = pnr / qv;
                    vii = pni / qv;
                }
                // Q[kp,m] -= v * q_m
                Q0.x -= vrr * qr[m0] - vii * qi[m0];
                Q0.y -= vrr * qi[m0] + vii * qr[m0];
                Q1.x -= vrr * qr[m1] - vii * qi[m1];
                Q1.y -= vrr * qi[m1] + vii * qr[m1];
            }
        }
        sQ[kp * 8 + m0] = Q0;
        sQ[kp * 8 + m1] = Q1;
    }
    __syncthreads();

    // ---- Qx = Q @ x ; xt = |Qx|^2 (unnormalized); local sum for scale ----
    // Q loaded per-iteration from SMEM (warp-uniform broadcast) to cut registers.
    float local = 0.f;
    float* out_xt = out + QELEMS + base;
    if (tid < 256) {
        int m = tid >> 5;
        int lane = tid & 31;
        #pragma unroll
        for (int j = 0; j < 4; j++) {
            int t = (lane + j * 32) * 4;    // 4 consecutive t's
            ull arA01 = 0, arA23 = 0;       // sum Qx*xr
            ull arB01 = 0, arB23 = 0;       // sum Qy*xi  (subtract at end)
            ull ai01 = 0, ai23 = 0;         // sum Qx*xi + Qy*xr
            #pragma unroll
            for (int n = 0; n < 8; n++) {
                float2 Qv = sQ[m * 8 + n];  // broadcast LDS.64
                ull Qxx = f2_pack(Qv.x, Qv.x);
                ull Qyy = f2_pack(Qv.y, Qv.y);
                ulonglong2 vr = *(const ulonglong2*)(sxr + n * XS + t);
                ulonglong2 vi = *(const ulonglong2*)(sxi + n * XS + t);
                arA01 = f2_fma(Qxx, vr.x, arA01);
                arA23 = f2_fma(Qxx, vr.y, arA23);
                arB01 = f2_fma(Qyy, vi.x, arB01);
                arB23 = f2_fma(Qyy, vi.y, arB23);
                ai01  = f2_fma(Qxx, vi.x, ai01);
                ai23  = f2_fma(Qxx, vi.y, ai23);
                ai01  = f2_fma(Qyy, vr.x, ai01);
                ai23  = f2_fma(Qyy, vr.y, ai23);
            }
            float a0,a1,a2,a3, b0,b1,b2,b3, i0,i1,i2,i3;
            f2_unpack(arA01, a0, a1); f2_unpack(arA23, a2, a3);
            f2_unpack(arB01, b0, b1); f2_unpack(arB23, b2, b3);
            f2_unpack(ai01,  i0, i1); f2_unpack(ai23,  i2, i3);
            float r0 = a0 - b0, r1 = a1 - b1, r2 = a2 - b2, r3 = a3 - b3;
            float4 v;
            v.x = r0 * r0 + i0 * i0;
            v.y = r1 * r1 + i1 * i1;
            v.z = r2 * r2 + i2 * i2;
            v.w = r3 * r3 + i3 * i3;
            local += v.x + v.y + v.z + v.w;
            *(float4*)(out_xt + m * TDIM + t) = v;
        }
    }
    // write unnormalized Q (real part only — output buffer is float32)
    if (tid < 64) {
        out[(size_t)bf * 64 + tid] = sQ[tid].x;
    }
    // deterministic fixed-order block reduction of `local`
    red[tid] = local;
    __syncthreads();
    for (int s = 144; s >= 9; s >>= 1) {
        if (tid < s) red[tid] += red[tid + s];
        __syncthreads();
    }
    if (tid == 0) {
        float s = 0.f;
        #pragma unroll
        for (int i = 0; i < 9; i++) s += red[i];
        g_partial[bf] = s;
    }
}

__global__ void iss_reduce()
{
    __shared__ float red[256];
    int b = blockIdx.x, tid = threadIdx.x;
    float s = 0.f;
    for (int i = tid; i < FDIM; i += 256) s += g_partial[b * FDIM + i];
    red[tid] = s;
    __syncthreads();
    for (int st = 128; st > 0; st >>= 1) {
        if (tid < st) red[tid] += red[tid + st];
        __syncthreads();
    }
    if (tid == 0) {
        float scale = red[0] / (float)PER_B_XT;
        g_xtscale[b] = 1.0f / scale;
        g_qscale[b]  = 1.0f / sqrtf(fmaxf(scale, 1e-6f));
    }
}

// single normalization pass over the whole output buffer (float4)
__global__ void iss_norm(float4* __restrict__ outv)
{
    size_t idx = (size_t)blockIdx.x * blockDim.x + threadIdx.x;
    if (idx >= (size_t)TOTAL4) return;
    float s;
    if (idx < (size_t)Q4) {
        s = g_qscale[(int)(idx / (PER_B_QE / 4))];
    } else {
        s = g_xtscale[(int)((idx - Q4) / (PER_B_XT / 4))];
    }
    float4 v = outv[idx];
    v.x *= s; v.y *= s; v.z *= s; v.w *= s;
    outv[idx] = v;
}

extern "C" void kernel_launch(void* const* d_in, const int* in_sizes, int n_in,
                              void* d_out, int out_size)
{
    const float* r  = (const float*)d_in[0];
    const float* Qr = (const float*)d_in[1];
    const float* Qi = (const float*)d_in[2];
    const float* xr = (const float*)d_in[3];
    const float* xi = (const float*)d_in[4];
    float* out = (float*)d_out;

    cudaFuncSetAttribute(iss_main, cudaFuncAttributeMaxDynamicSharedMemorySize, SMEM_BYTES);

    iss_main<<<NBF, NTHREADS, SMEM_BYTES>>>(r, Qr, Qi, xr, xi, out);
    iss_reduce<<<BDIM, 256>>>();
    iss_norm<<<(TOTAL4 + 255) / 256, 256>>>((float4*)out);
}

// round 7
// speedup vs baseline: 1.2284x; 1.0984x over previous
#include <cuda_runtime.h>
#include <math.h>

#define BDIM 8
#define FDIM 1025
#define MDIM 8
#define TDIM 512
#define NBF (BDIM * FDIM)            // 8200
#define NTHREADS 256
#define XS 516                        // padded SMEM row stride (16B-aligned rows)

#define QELEMS (NBF * MDIM * MDIM)           // 524,800  (Q stored as real part only)
#define XTCOUNT (NBF * MDIM * TDIM)          // 33,587,200
#define PER_B_XT (FDIM * MDIM * TDIM)        // 4,198,400
#define PER_B_QE (FDIM * MDIM * MDIM)        // 65,600
#define TOTAL4 ((QELEMS + XTCOUNT) / 4)      // 8,528,000 float4s
#define Q4 (QELEMS / 4)                      // 131,200

// SMEM layout (float offsets). part ALIASES sr (r is dead after V-accum).
#define OFF_SXR 0
#define OFF_SXI (OFF_SXR + MDIM * XS)        // 4128
#define OFF_SR  (OFF_SXI + MDIM * XS)        // 8256  (4128 floats)
#define OFF_PART OFF_SR                      // 4096 floats, aliased
#define OFF_V   (OFF_SR + MDIM * XS)         // 12384 (512 float2)
#define OFF_SQ  (OFF_V + 1024)               // 13408 (64 float2)
#define OFF_RED (OFF_SQ + 128)               // 13536 (256 floats)
#define SMEM_FLOATS (OFF_RED + NTHREADS)     // 13792
#define SMEM_BYTES (SMEM_FLOATS * 4)         // 55,168 B -> 4 blocks/SM

typedef unsigned long long ull;
#define SGN2 0x8000000080000000ULL

__device__ __forceinline__ ull f2_pack(float lo, float hi) {
    ull r; asm("mov.b64 %0,{%1,%2};" : "=l"(r) : "f"(lo), "f"(hi)); return r;
}
__device__ __forceinline__ void f2_unpack(ull v, float& lo, float& hi) {
    asm("mov.b64 {%0,%1},%2;" : "=f"(lo), "=f"(hi) : "l"(v));
}
__device__ __forceinline__ ull f2_fma(ull a, ull b, ull c) {
    ull d; asm("fma.rn.f32x2 %0,%1,%2,%3;" : "=l"(d) : "l"(a), "l"(b), "l"(c)); return d;
}
__device__ __forceinline__ ull f2_mul(ull a, ull b) {
    ull d; asm("mul.rn.f32x2 %0,%1,%2;" : "=l"(d) : "l"(a), "l"(b)); return d;
}

__device__ float g_partial[NBF];
__device__ float g_xtscale[BDIM];
__device__ float g_qscale[BDIM];

// 28 strict upper-triangle pairs (m < n)
__constant__ unsigned char c_pm[28] = {
    0,0,0,0,0,0,0,
    1,1,1,1,1,1,
    2,2,2,2,2,
    3,3,3,3,
    4,4,4,
    5,5,
    6};
__constant__ unsigned char c_pn[28] = {
    1,2,3,4,5,6,7,
    2,3,4,5,6,7,
    3,4,5,6,7,
    4,5,6,7,
    5,6,7,
    6,7,
    7};

__global__ __launch_bounds__(NTHREADS, 4)
void iss_main(const float* __restrict__ r,
              const float* __restrict__ Qr,
              const float* __restrict__ Qi,
              const float* __restrict__ xr,
              const float* __restrict__ xi,
              float* __restrict__ out)
{
    extern __shared__ float sm[];
    float*  sxr  = sm + OFF_SXR;
    float*  sxi  = sm + OFF_SXI;
    float*  sr   = sm + OFF_SR;
    float2* part = (float2*)(sm + OFF_PART);  // [slot][k][chunk], aliases sr
    float2* V    = (float2*)(sm + OFF_V);     // [k][m][n]
    float2* sQ   = (float2*)(sm + OFF_SQ);    // [k][m]
    float*  red  = sm + OFF_RED;

    const int tid = threadIdx.x;
    const int bf = blockIdx.x;
    const size_t base = (size_t)bf * (MDIM * TDIM);

    // ---- stage inputs in SMEM via float4 (r clipped at load) ----
    {
        const float4* xr4 = (const float4*)(xr + base);
        const float4* xi4 = (const float4*)(xi + base);
        const float4* r4  = (const float4*)(r + base);
        for (int i = tid; i < MDIM * TDIM / 4; i += NTHREADS) {
            int m = i >> 7, t4 = (i & 127) << 2;
            float4 a = xr4[i];
            *(float4*)(sxr + m * XS + t4) = a;
            float4 b = xi4[i];
            *(float4*)(sxi + m * XS + t4) = b;
            float4 c = r4[i];
            c.x = fmaxf(c.x, 1e-3f); c.y = fmaxf(c.y, 1e-3f);
            c.z = fmaxf(c.z, 1e-3f); c.w = fmaxf(c.w, 1e-3f);
            *(float4*)(sr + m * XS + t4) = c;
        }
    }
    if (tid < 64) {
        sQ[tid] = make_float2(Qr[(size_t)bf * 64 + tid], Qi[(size_t)bf * 64 + tid]);
    }
    __syncthreads();

    // ---- V accumulation. warp == chunk (64 t's). slot = lane. ----
    // slots 0..27: Hermitian pair (m<n): acc.x=Re, acc.y=Im of r_k * x_m * conj(x_n)
    // slots 28..31: diag-double d=slot-28: acc.x = r_k*|x_d|^2, acc.y = r_k*|x_{d+4}|^2
    ull accx[8], accy[8];
    {
        const int chunk = tid >> 5;
        const int slot  = tid & 31;
        const bool offd = slot < 28;
        int m, n;
        if (offd) { m = c_pm[slot]; n = c_pn[slot]; }
        else      { m = slot - 28;  n = slot - 24; }
        const ulonglong2* pxrm = (const ulonglong2*)(sxr + m * XS + chunk * 64);
        const ulonglong2* pxim = (const ulonglong2*)(sxi + m * XS + chunk * 64);
        const ulonglong2* pxrn = (const ulonglong2*)(sxr + n * XS + chunk * 64);
        const ulonglong2* pxin = (const ulonglong2*)(sxi + n * XS + chunk * 64);
        const float* srl = sr + chunk * 64;

        #pragma unroll
        for (int k = 0; k < 8; k++) { accx[k] = 0ULL; accy[k] = 0ULL; }

        #pragma unroll 2
        for (int q = 0; q < 16; q++) {            // q indexes groups of 4 t's
            ulonglong2 vrm = pxrm[q];
            ulonglong2 vim = pxim[q];
            ulonglong2 vrn = pxrn[q];
            ulonglong2 vin = pxin[q];
            ull a01, a23, b01, b23;
            if (offd) {
                a01 = f2_fma(vrm.x, vrn.x, f2_mul(vim.x, vin.x));
                a23 = f2_fma(vrm.y, vrn.y, f2_mul(vim.y, vin.y));
                b01 = f2_fma(vim.x, vrn.x, f2_mul(vrm.x ^ SGN2, vin.x));
                b23 = f2_fma(vim.y, vrn.y, f2_mul(vrm.y ^ SGN2, vin.y));
            } else {
                a01 = f2_fma(vrm.x, vrm.x, f2_mul(vim.x, vim.x));
                a23 = f2_fma(vrm.y, vrm.y, f2_mul(vim.y, vim.y));
                b01 = f2_fma(vrn.x, vrn.x, f2_mul(vin.x, vin.x));
                b23 = f2_fma(vrn.y, vrn.y, f2_mul(vin.y, vin.y));
            }
            #pragma unroll
            for (int k = 0; k < 8; k++) {
                ulonglong2 rk = *(const ulonglong2*)(srl + k * XS + q * 4);
                accx[k] = f2_fma(rk.x, a01, accx[k]);
                accx[k] = f2_fma(rk.y, a23, accx[k]);
                accy[k] = f2_fma(rk.x, b01, accy[k]);
                accy[k] = f2_fma(rk.y, b23, accy[k]);
            }
        }
    }
    __syncthreads();   // all sr reads complete before part (aliased) is written

    {
        const int chunk = tid >> 5;
        const int slot  = tid & 31;
        #pragma unroll
        for (int k = 0; k < 8; k++) {
            float xl, xh, yl, yh;
            f2_unpack(accx[k], xl, xh);
            f2_unpack(accy[k], yl, yh);
            part[(slot * 8 + k) * 8 + chunk] = make_float2(xl + xh, yl + yh);
        }
    }
    __syncthreads();

    // reduce over chunks, fill V. 32 slots * 8 k = 256 items exactly.
    {
        int slot = tid >> 3, k = tid & 7;
        float2 s = make_float2(0.f, 0.f);
        #pragma unroll
        for (int c = 0; c < 8; c++) {
            float2 p = part[(slot * 8 + k) * 8 + c];
            s.x += p.x; s.y += p.y;
        }
        s.x *= (1.0f / TDIM);
        s.y *= (1.0f / TDIM);
        if (slot < 28) {
            int m = c_pm[slot], n = c_pn[slot];
            V[(k * 8 + m) * 8 + n] = s;
            V[(k * 8 + n) * 8 + m] = make_float2(s.x, -s.y);
        } else {
            int d = slot - 28;
            V[(k * 8 + d) * 8 + d]           = make_float2(s.x, 0.f);
            V[(k * 8 + d + 4) * 8 + d + 4]   = make_float2(s.y, 0.f);
        }
    }
    __syncthreads();

    // trV + diagonal regularization
    if (tid < 8) {
        int k = tid;
        float tr = 0.f;
        #pragma unroll
        for (int m = 0; m < 8; m++) tr += V[(k * 8 + m) * 8 + m].x;
        float reg = fmaxf(tr, 1.0f) * 1e-6f;
        #pragma unroll
        for (int m = 0; m < 8; m++) V[(k * 8 + m) * 8 + m].x += reg;
    }
    __syncthreads();

    // ---- 2 x 8 sweep, fully register-resident on warp 0 ----
    if (tid < 32) {
        const int lane = tid;
        const int kp = lane >> 2;
        const int j  = lane & 3;
        const int m0 = 2 * j, m1 = 2 * j + 1;

        float2 Vr0[8], Vr1[8];
        #pragma unroll
        for (int n = 0; n < 8; n++) {
            Vr0[n] = V[(kp * 8 + m0) * 8 + n];
            Vr1[n] = V[(kp * 8 + m1) * 8 + n];
        }
        float2 Q0 = sQ[kp * 8 + m0];
        float2 Q1 = sQ[kp * 8 + m1];

        #pragma unroll 1
        for (int it = 0; it < 2; it++) {
            #pragma unroll 1
            for (int k = 0; k < 8; k++) {
                float qr[8], qi[8];
                #pragma unroll
                for (int jp = 0; jp < 4; jp++) {
                    int src = k * 4 + jp;
                    qr[2 * jp]     = __shfl_sync(0xffffffffu, Q0.x, src);
                    qi[2 * jp]     = __shfl_sync(0xffffffffu, Q0.y, src);
                    qr[2 * jp + 1] = __shfl_sync(0xffffffffu, Q1.x, src);
                    qi[2 * jp + 1] = __shfl_sync(0xffffffffu, Q1.y, src);
                }
                float vq0r = 0.f, vq0i = 0.f, vq1r = 0.f, vq1i = 0.f;
                #pragma unroll
                for (int n = 0; n < 8; n++) {
                    vq0r += Vr0[n].x * qr[n] + Vr0[n].y * qi[n];
                    vq0i += Vr0[n].y * qr[n] - Vr0[n].x * qi[n];
                    vq1r += Vr1[n].x * qr[n] + Vr1[n].y * qi[n];
                    vq1i += Vr1[n].y * qr[n] - Vr1[n].x * qi[n];
                }
                float pq  = qr[m0] * vq0r - qi[m0] * vq0i
                          + qr[m1] * vq1r - qi[m1] * vq1i;
                float pnr = Q0.x * vq0r - Q0.y * vq0i
                          + Q1.x * vq1r - Q1.y * vq1i;
                float pni = Q0.x * vq0i + Q0.y * vq0r
                          + Q1.x * vq1i + Q1.y * vq1r;
                pq  += __shfl_xor_sync(0xffffffffu, pq, 1);
                pnr += __shfl_xor_sync(0xffffffffu, pnr, 1);
                pni += __shfl_xor_sync(0xffffffffu, pni, 1);
                pq  += __shfl_xor_sync(0xffffffffu, pq, 2);
                pnr += __shfl_xor_sync(0xffffffffu, pnr, 2);
                pni += __shfl_xor_sync(0xffffffffu, pni, 2);

                float qv = fmaxf(pq, 1e-6f);
                float vrr, vii;
                if (kp == k) {
                    vrr = 1.0f - 1.0f / sqrtf(qv);
                    vii = 0.0f;
                } else {
                    vrr = pnr / qv;
                    vii = pni / qv;
                }
                Q0.x -= vrr * qr[m0] - vii * qi[m0];
                Q0.y -= vrr * qi[m0] + vii * qr[m0];
                Q1.x -= vrr * qr[m1] - vii * qi[m1];
                Q1.y -= vrr * qi[m1] + vii * qr[m1];
            }
        }
        sQ[kp * 8 + m0] = Q0;
        sQ[kp * 8 + m1] = Q1;
    }
    __syncthreads();

    // ---- Qx = Q @ x ; xt = |Qx|^2 (unnormalized); local sum for scale ----
    float local = 0.f;
    float* out_xt = out + QELEMS + base;
    {
        int m = tid >> 5;
        int lane = tid & 31;
        #pragma unroll
        for (int j = 0; j < 4; j++) {
            int t = (lane + j * 32) * 4;    // 4 consecutive t's
            ull arA01 = 0, arA23 = 0;       // sum Qx*xr
            ull arB01 = 0, arB23 = 0;       // sum Qy*xi  (subtract at end)
            ull ai01 = 0, ai23 = 0;         // sum Qx*xi + Qy*xr
            #pragma unroll
            for (int n = 0; n < 8; n++) {
                float2 Qv = sQ[m * 8 + n];  // broadcast LDS.64
                ull Qxx = f2_pack(Qv.x, Qv.x);
                ull Qyy = f2_pack(Qv.y, Qv.y);
                ulonglong2 vr = *(const ulonglong2*)(sxr + n * XS + t);
                ulonglong2 vi = *(const ulonglong2*)(sxi + n * XS + t);
                arA01 = f2_fma(Qxx, vr.x, arA01);
                arA23 = f2_fma(Qxx, vr.y, arA23);
                arB01 = f2_fma(Qyy, vi.x, arB01);
                arB23 = f2_fma(Qyy, vi.y, arB23);
                ai01  = f2_fma(Qxx, vi.x, ai01);
                ai23  = f2_fma(Qxx, vi.y, ai23);
                ai01  = f2_fma(Qyy, vr.x, ai01);
                ai23  = f2_fma(Qyy, vr.y, ai23);
            }
            float a0,a1,a2,a3, b0,b1,b2,b3, i0,i1,i2,i3;
            f2_unpack(arA01, a0, a1); f2_unpack(arA23, a2, a3);
            f2_unpack(arB01, b0, b1); f2_unpack(arB23, b2, b3);
            f2_unpack(ai01,  i0, i1); f2_unpack(ai23,  i2, i3);
            float r0 = a0 - b0, r1 = a1 - b1, r2 = a2 - b2, r3 = a3 - b3;
            float4 v;
            v.x = r0 * r0 + i0 * i0;
            v.y = r1 * r1 + i1 * i1;
            v.z = r2 * r2 + i2 * i2;
            v.w = r3 * r3 + i3 * i3;
            local += v.x + v.y + v.z + v.w;
            *(float4*)(out_xt + m * TDIM + t) = v;
        }
    }
    // write unnormalized Q (real part only — output buffer is float32)
    if (tid < 64) {
        out[(size_t)bf * 64 + tid] = sQ[tid].x;
    }
    // deterministic fixed-order block reduction of `local`
    red[tid] = local;
    __syncthreads();
    #pragma unroll
    for (int s = 128; s > 0; s >>= 1) {
        if (tid < s) red[tid] += red[tid + s];
        __syncthreads();
    }
    if (tid == 0) {
        g_partial[bf] = red[0];
    }
}

__global__ void iss_reduce()
{
    __shared__ float red[256];
    int b = blockIdx.x, tid = threadIdx.x;
    float s = 0.f;
    for (int i = tid; i < FDIM; i += 256) s += g_partial[b * FDIM + i];
    red[tid] = s;
    __syncthreads();
    for (int st = 128; st > 0; st >>= 1) {
        if (tid < st) red[tid] += red[tid + st];
        __syncthreads();
    }
    if (tid == 0) {
        float scale = red[0] / (float)PER_B_XT;
        g_xtscale[b] = 1.0f / scale;
        g_qscale[b]  = 1.0f / sqrtf(fmaxf(scale, 1e-6f));
    }
}

// single normalization pass over the whole output buffer (float4)
__global__ void iss_norm(float4* __restrict__ outv)
{
    size_t idx = (size_t)blockIdx.x * blockDim.x + threadIdx.x;
    if (idx >= (size_t)TOTAL4) return;
    float s;
    if (idx < (size_t)Q4) {
        s = g_qscale[(int)(idx / (PER_B_QE / 4))];
    } else {
        s = g_xtscale[(int)((idx - Q4) / (PER_B_XT / 4))];
    }
    float4 v = outv[idx];
    v.x *= s; v.y *= s; v.z *= s; v.w *= s;
    outv[idx] = v;
}

extern "C" void kernel_launch(void* const* d_in, const int* in_sizes, int n_in,
                              void* d_out, int out_size)
{
    const float* r  = (const float*)d_in[0];
    const float* Qr = (const float*)d_in[1];
    const float* Qi = (const float*)d_in[2];
    const float* xr = (const float*)d_in[3];
    const float* xi = (const float*)d_in[4];
    float* out = (float*)d_out;

    cudaFuncSetAttribute(iss_main, cudaFuncAttributeMaxDynamicSharedMemorySize, SMEM_BYTES);

    iss_main<<<NBF, NTHREADS, SMEM_BYTES>>>(r, Qr, Qi, xr, xi, out);
    iss_reduce<<<BDIM, 256>>>();
    iss_norm<<<(TOTAL4 + 255) / 256, 256>>>((float4*)out);
}

// round 8
// speedup vs baseline: 1.2616x; 1.0270x over previous
#include <cuda_runtime.h>
#include <math.h>

#define BDIM 8
#define FDIM 1025
#define MDIM 8
#define TDIM 512
#define NBF (BDIM * FDIM)            // 8200
#define NTHREADS 256
#define XS 516                        // padded SMEM row stride (16B-aligned rows)

#define QELEMS (NBF * MDIM * MDIM)           // 524,800  (Q stored as real part only)
#define XTCOUNT (NBF * MDIM * TDIM)          // 33,587,200
#define PER_B_XT (FDIM * MDIM * TDIM)        // 4,198,400
#define PER_B_QE (FDIM * MDIM * MDIM)        // 65,600
#define TOTAL4 ((QELEMS + XTCOUNT) / 4)      // 8,528,000 float4s
#define Q4 (QELEMS / 4)                      // 131,200

// SMEM layout (float offsets). part ALIASES sr (r is dead after V-accum).
#define OFF_SXR 0
#define OFF_SXI (OFF_SXR + MDIM * XS)        // 4128
#define OFF_SR  (OFF_SXI + MDIM * XS)        // 8256  (4128 floats)
#define OFF_PART OFF_SR                      // 4096 floats, aliased
#define OFF_V   (OFF_SR + MDIM * XS)         // 12384 (512 float2)
#define OFF_SQ  (OFF_V + 1024)               // 13408 (64 float2)
#define OFF_RED (OFF_SQ + 128)               // 13536 (256 floats)
#define SMEM_FLOATS (OFF_RED + NTHREADS)     // 13792
#define SMEM_BYTES (SMEM_FLOATS * 4)         // 55,168 B -> 4 blocks/SM

typedef unsigned long long ull;
#define SGN2 0x8000000080000000ULL

__device__ __forceinline__ ull f2_pack(float lo, float hi) {
    ull r; asm("mov.b64 %0,{%1,%2};" : "=l"(r) : "f"(lo), "f"(hi)); return r;
}
__device__ __forceinline__ void f2_unpack(ull v, float& lo, float& hi) {
    asm("mov.b64 {%0,%1},%2;" : "=f"(lo), "=f"(hi) : "l"(v));
}
__device__ __forceinline__ ull f2_fma(ull a, ull b, ull c) {
    ull d; asm("fma.rn.f32x2 %0,%1,%2,%3;" : "=l"(d) : "l"(a), "l"(b), "l"(c)); return d;
}
__device__ __forceinline__ ull f2_mul(ull a, ull b) {
    ull d; asm("mul.rn.f32x2 %0,%1,%2;" : "=l"(d) : "l"(a), "l"(b)); return d;
}

__device__ float g_partial[NBF];
__device__ float g_xtscale[BDIM];
__device__ float g_qscale[BDIM];

// 28 strict upper-triangle pairs (m < n)
__constant__ unsigned char c_pm[28] = {
    0,0,0,0,0,0,0,
    1,1,1,1,1,1,
    2,2,2,2,2,
    3,3,3,3,
    4,4,4,
    5,5,
    6};
__constant__ unsigned char c_pn[28] = {
    1,2,3,4,5,6,7,
    2,3,4,5,6,7,
    3,4,5,6,7,
    4,5,6,7,
    5,6,7,
    6,7,
    7};

__global__ __launch_bounds__(NTHREADS, 4)
void iss_main(const float* __restrict__ r,
              const float* __restrict__ Qr,
              const float* __restrict__ Qi,
              const float* __restrict__ xr,
              const float* __restrict__ xi,
              float* __restrict__ out)
{
    extern __shared__ float sm[];
    float*  sxr  = sm + OFF_SXR;
    float*  sxi  = sm + OFF_SXI;
    float*  sr   = sm + OFF_SR;
    float2* part = (float2*)(sm + OFF_PART);  // [slot][k][chunk], aliases sr
    float2* V    = (float2*)(sm + OFF_V);     // [k][m][n]
    float2* sQ   = (float2*)(sm + OFF_SQ);    // [k][m]
    float*  red  = sm + OFF_RED;

    const int tid = threadIdx.x;
    const int bf = blockIdx.x;
    const size_t base = (size_t)bf * (MDIM * TDIM);

    // ---- stage inputs in SMEM via float4 (r clipped at load) ----
    {
        const float4* xr4 = (const float4*)(xr + base);
        const float4* xi4 = (const float4*)(xi + base);
        const float4* r4  = (const float4*)(r + base);
        for (int i = tid; i < MDIM * TDIM / 4; i += NTHREADS) {
            int m = i >> 7, t4 = (i & 127) << 2;
            float4 a = xr4[i];
            *(float4*)(sxr + m * XS + t4) = a;
            float4 b = xi4[i];
            *(float4*)(sxi + m * XS + t4) = b;
            float4 c = r4[i];
            c.x = fmaxf(c.x, 1e-3f); c.y = fmaxf(c.y, 1e-3f);
            c.z = fmaxf(c.z, 1e-3f); c.w = fmaxf(c.w, 1e-3f);
            *(float4*)(sr + m * XS + t4) = c;
        }
    }
    if (tid < 64) {
        sQ[tid] = make_float2(Qr[(size_t)bf * 64 + tid], Qi[(size_t)bf * 64 + tid]);
    }
    __syncthreads();

    // ---- V accumulation. warp == chunk (64 t's). slot = lane. ----
    ull accx[8], accy[8];
    {
        const int chunk = tid >> 5;
        const int slot  = tid & 31;
        const bool offd = slot < 28;
        int m, n;
        if (offd) { m = c_pm[slot]; n = c_pn[slot]; }
        else      { m = slot - 28;  n = slot - 24; }
        const ulonglong2* pxrm = (const ulonglong2*)(sxr + m * XS + chunk * 64);
        const ulonglong2* pxim = (const ulonglong2*)(sxi + m * XS + chunk * 64);
        const ulonglong2* pxrn = (const ulonglong2*)(sxr + n * XS + chunk * 64);
        const ulonglong2* pxin = (const ulonglong2*)(sxi + n * XS + chunk * 64);
        const float* srl = sr + chunk * 64;

        #pragma unroll
        for (int k = 0; k < 8; k++) { accx[k] = 0ULL; accy[k] = 0ULL; }

        #pragma unroll 2
        for (int q = 0; q < 16; q++) {            // q indexes groups of 4 t's
            ulonglong2 vrm = pxrm[q];
            ulonglong2 vim = pxim[q];
            ulonglong2 vrn = pxrn[q];
            ulonglong2 vin = pxin[q];
            ull a01, a23, b01, b23;
            if (offd) {
                a01 = f2_fma(vrm.x, vrn.x, f2_mul(vim.x, vin.x));
                a23 = f2_fma(vrm.y, vrn.y, f2_mul(vim.y, vin.y));
                b01 = f2_fma(vim.x, vrn.x, f2_mul(vrm.x ^ SGN2, vin.x));
                b23 = f2_fma(vim.y, vrn.y, f2_mul(vrm.y ^ SGN2, vin.y));
            } else {
                a01 = f2_fma(vrm.x, vrm.x, f2_mul(vim.x, vim.x));
                a23 = f2_fma(vrm.y, vrm.y, f2_mul(vim.y, vim.y));
                b01 = f2_fma(vrn.x, vrn.x, f2_mul(vin.x, vin.x));
                b23 = f2_fma(vrn.y, vrn.y, f2_mul(vin.y, vin.y));
            }
            #pragma unroll
            for (int k = 0; k < 8; k++) {
                ulonglong2 rk = *(const ulonglong2*)(srl + k * XS + q * 4);
                accx[k] = f2_fma(rk.x, a01, accx[k]);
                accx[k] = f2_fma(rk.y, a23, accx[k]);
                accy[k] = f2_fma(rk.x, b01, accy[k]);
                accy[k] = f2_fma(rk.y, b23, accy[k]);
            }
        }
    }
    __syncthreads();   // all sr reads complete before part (aliased) is written

    {
        const int chunk = tid >> 5;
        const int slot  = tid & 31;
        #pragma unroll
        for (int k = 0; k < 8; k++) {
            float xl, xh, yl, yh;
            f2_unpack(accx[k], xl, xh);
            f2_unpack(accy[k], yl, yh);
            part[(slot * 8 + k) * 8 + chunk] = make_float2(xl + xh, yl + yh);
        }
    }
    __syncthreads();

    // reduce over chunks, fill V. 32 slots * 8 k = 256 items exactly.
    {
        int slot = tid >> 3, k = tid & 7;
        float2 s = make_float2(0.f, 0.f);
        #pragma unroll
        for (int c = 0; c < 8; c++) {
            float2 p = part[(slot * 8 + k) * 8 + c];
            s.x += p.x; s.y += p.y;
        }
        s.x *= (1.0f / TDIM);
        s.y *= (1.0f / TDIM);
        if (slot < 28) {
            int m = c_pm[slot], n = c_pn[slot];
            V[(k * 8 + m) * 8 + n] = s;
            V[(k * 8 + n) * 8 + m] = make_float2(s.x, -s.y);
        } else {
            int d = slot - 28;
            V[(k * 8 + d) * 8 + d]           = make_float2(s.x, 0.f);
            V[(k * 8 + d + 4) * 8 + d + 4]   = make_float2(s.y, 0.f);
        }
    }
    __syncthreads();

    // trV + diagonal regularization
    if (tid < 8) {
        int k = tid;
        float tr = 0.f;
        #pragma unroll
        for (int m = 0; m < 8; m++) tr += V[(k * 8 + m) * 8 + m].x;
        float reg = fmaxf(tr, 1.0f) * 1e-6f;
        #pragma unroll
        for (int m = 0; m < 8; m++) V[(k * 8 + m) * 8 + m].x += reg;
    }
    __syncthreads();

    // ---- 2 x 8 sweep, fully register-resident on warp 0 ----
    if (tid < 32) {
        const int lane = tid;
        const int kp = lane >> 2;
        const int j  = lane & 3;
        const int m0 = 2 * j, m1 = 2 * j + 1;

        float2 Vr0[8], Vr1[8];
        #pragma unroll
        for (int n = 0; n < 8; n++) {
            Vr0[n] = V[(kp * 8 + m0) * 8 + n];
            Vr1[n] = V[(kp * 8 + m1) * 8 + n];
        }
        float2 Q0 = sQ[kp * 8 + m0];
        float2 Q1 = sQ[kp * 8 + m1];

        #pragma unroll 1
        for (int it = 0; it < 2; it++) {
            #pragma unroll 1
            for (int k = 0; k < 8; k++) {
                float qr[8], qi[8];
                #pragma unroll
                for (int jp = 0; jp < 4; jp++) {
                    int src = k * 4 + jp;
                    qr[2 * jp]     = __shfl_sync(0xffffffffu, Q0.x, src);
                    qi[2 * jp]     = __shfl_sync(0xffffffffu, Q0.y, src);
                    qr[2 * jp + 1] = __shfl_sync(0xffffffffu, Q1.x, src);
                    qi[2 * jp + 1] = __shfl_sync(0xffffffffu, Q1.y, src);
                }
                float vq0r = 0.f, vq0i = 0.f, vq1r = 0.f, vq1i = 0.f;
                #pragma unroll
                for (int n = 0; n < 8; n++) {
                    vq0r += Vr0[n].x * qr[n] + Vr0[n].y * qi[n];
                    vq0i += Vr0[n].y * qr[n] - Vr0[n].x * qi[n];
                    vq1r += Vr1[n].x * qr[n] + Vr1[n].y * qi[n];
                    vq1i += Vr1[n].y * qr[n] - Vr1[n].x * qi[n];
                }
                float pq  = qr[m0] * vq0r - qi[m0] * vq0i
                          + qr[m1] * vq1r - qi[m1] * vq1i;
                float pnr = Q0.x * vq0r - Q0.y * vq0i
                          + Q1.x * vq1r - Q1.y * vq1i;
                float pni = Q0.x * vq0i + Q0.y * vq0r
                          + Q1.x * vq1i + Q1.y * vq1r;
                pq  += __shfl_xor_sync(0xffffffffu, pq, 1);
                pnr += __shfl_xor_sync(0xffffffffu, pnr, 1);
                pni += __shfl_xor_sync(0xffffffffu, pni, 1);
                pq  += __shfl_xor_sync(0xffffffffu, pq, 2);
                pnr += __shfl_xor_sync(0xffffffffu, pnr, 2);
                pni += __shfl_xor_sync(0xffffffffu, pni, 2);

                float qv = fmaxf(pq, 1e-6f);
                float vrr, vii;
                if (kp == k) {
                    vrr = 1.0f - 1.0f / sqrtf(qv);
                    vii = 0.0f;
                } else {
                    vrr = pnr / qv;
                    vii = pni / qv;
                }
                Q0.x -= vrr * qr[m0] - vii * qi[m0];
                Q0.y -= vrr * qi[m0] + vii * qr[m0];
                Q1.x -= vrr * qr[m1] - vii * qi[m1];
                Q1.y -= vrr * qi[m1] + vii * qr[m1];
            }
        }
        sQ[kp * 8 + m0] = Q0;
        sQ[kp * 8 + m1] = Q1;
    }
    __syncthreads();

    // ---- Qx = Q @ x ; xt = |Qx|^2. Transposed decomposition:
    // warp = t-chunk (64 t), lane = 2 consecutive t's; all 8 m in registers.
    // x read ONCE from SMEM per warp; Q via 1-wavefront broadcast loads.
    float local = 0.f;
    float* out_xt = out + QELEMS + base;
    {
        const int chunk = tid >> 5;
        const int lane = tid & 31;
        const int t = chunk * 64 + lane * 2;

        ull arP[8], aiP[8];
        #pragma unroll
        for (int m = 0; m < 8; m++) { arP[m] = 0ULL; aiP[m] = 0ULL; }

        #pragma unroll
        for (int n = 0; n < 8; n++) {
            ull vr  = *(const ull*)(sxr + n * XS + t);
            ull vi  = *(const ull*)(sxi + n * XS + t);
            ull vin = vi ^ SGN2;      // -xi for the ar accumulation
            #pragma unroll
            for (int m = 0; m < 8; m++) {
                float2 Qv = sQ[m * 8 + n];     // broadcast LDS.64 (1 wf)
                ull Qxx = f2_pack(Qv.x, Qv.x);
                ull Qyy = f2_pack(Qv.y, Qv.y);
                arP[m] = f2_fma(Qxx, vr, f2_fma(Qyy, vin, arP[m]));
                aiP[m] = f2_fma(Qxx, vi, f2_fma(Qyy, vr,  aiP[m]));
            }
        }
        #pragma unroll
        for (int m = 0; m < 8; m++) {
            float r0, r1, i0, i1;
            f2_unpack(arP[m], r0, r1);
            f2_unpack(aiP[m], i0, i1);
            float v0 = r0 * r0 + i0 * i0;
            float v1 = r1 * r1 + i1 * i1;
            local += v0 + v1;
            *(float2*)(out_xt + m * TDIM + t) = make_float2(v0, v1);
        }
    }
    // write unnormalized Q (real part only — output buffer is float32)
    if (tid < 64) {
        out[(size_t)bf * 64 + tid] = sQ[tid].x;
    }
    // deterministic fixed-order block reduction of `local`
    red[tid] = local;
    __syncthreads();
    #pragma unroll
    for (int s = 128; s > 0; s >>= 1) {
        if (tid < s) red[tid] += red[tid + s];
        __syncthreads();
    }
    if (tid == 0) {
        g_partial[bf] = red[0];
    }
}

__global__ void iss_reduce()
{
    __shared__ float red[256];
    int b = blockIdx.x, tid = threadIdx.x;
    float s = 0.f;
    for (int i = tid; i < FDIM; i += 256) s += g_partial[b * FDIM + i];
    red[tid] = s;
    __syncthreads();
    for (int st = 128; st > 0; st >>= 1) {
        if (tid < st) red[tid] += red[tid + st];
        __syncthreads();
    }
    if (tid == 0) {
        float scale = red[0] / (float)PER_B_XT;
        g_xtscale[b] = 1.0f / scale;
        g_qscale[b]  = 1.0f / sqrtf(fmaxf(scale, 1e-6f));
    }
}

// single normalization pass over the whole output buffer (float4)
__global__ void iss_norm(float4* __restrict__ outv)
{
    size_t idx = (size_t)blockIdx.x * blockDim.x + threadIdx.x;
    if (idx >= (size_t)TOTAL4) return;
    float s;
    if (idx < (size_t)Q4) {
        s = g_qscale[(int)(idx / (PER_B_QE / 4))];
    } else {
        s = g_xtscale[(int)((idx - Q4) / (PER_B_XT / 4))];
    }
    float4 v = outv[idx];
    v.x *= s; v.y *= s; v.z *= s; v.w *= s;
    outv[idx] = v;
}

extern "C" void kernel_launch(void* const* d_in, const int* in_sizes, int n_in,
                              void* d_out, int out_size)
{
    const float* r  = (const float*)d_in[0];
    const float* Qr = (const float*)d_in[1];
    const float* Qi = (const float*)d_in[2];
    const float* xr = (const float*)d_in[3];
    const float* xi = (const float*)d_in[4];
    float* out = (float*)d_out;

    cudaFuncSetAttribute(iss_main, cudaFuncAttributeMaxDynamicSharedMemorySize, SMEM_BYTES);

    iss_main<<<NBF, NTHREADS, SMEM_BYTES>>>(r, Qr, Qi, xr, xi, out);
    iss_reduce<<<BDIM, 256>>>();
    iss_norm<<<(TOTAL4 + 255) / 256, 256>>>((float4*)out);
}

// round 9
// speedup vs baseline: 1.3181x; 1.0448x over previous
#include <cuda_runtime.h>
#include <math.h>

#define BDIM 8
#define FDIM 1025
#define MDIM 8
#define TDIM 512
#define NBF (BDIM * FDIM)            // 8200
#define NTHREADS 256
#define XS 516                        // padded SMEM row stride (16B-aligned rows)

#define QELEMS (NBF * MDIM * MDIM)           // 524,800  (Q stored as real part only)
#define XTCOUNT (NBF * MDIM * TDIM)          // 33,587,200
#define PER_B_XT (FDIM * MDIM * TDIM)        // 4,198,400
#define PER_B_QE (FDIM * MDIM * MDIM)        // 65,600
#define TOTAL4 ((QELEMS + XTCOUNT) / 4)      // 8,528,000 float4s
#define Q4 (QELEMS / 4)                      // 131,200

// SMEM layout (float offsets). part ALIASES sr (r is dead after V-accum).
#define OFF_SXR 0
#define OFF_SXI (OFF_SXR + MDIM * XS)        // 4128
#define OFF_SR  (OFF_SXI + MDIM * XS)        // 8256  (4128 floats)
#define OFF_PART OFF_SR                      // 4096 floats, aliased
#define OFF_V   (OFF_SR + MDIM * XS)         // 12384 (512 float2)
#define OFF_SQ  (OFF_V + 1024)               // 13408 (64 float2)
#define OFF_SQP (OFF_SQ + 128)               // 13536 (64 ulonglong2 = 256 floats)
#define OFF_RED (OFF_SQP + 256)              // 13792 (8 floats)
#define SMEM_FLOATS (OFF_RED + 8)            // 13800
#define SMEM_BYTES (SMEM_FLOATS * 4)         // 55,200 B -> 4 blocks/SM

typedef unsigned long long ull;
#define SGN2 0x8000000080000000ULL

__device__ __forceinline__ ull f2_pack(float lo, float hi) {
    ull r; asm("mov.b64 %0,{%1,%2};" : "=l"(r) : "f"(lo), "f"(hi)); return r;
}
__device__ __forceinline__ void f2_unpack(ull v, float& lo, float& hi) {
    asm("mov.b64 {%0,%1},%2;" : "=f"(lo), "=f"(hi) : "l"(v));
}
__device__ __forceinline__ ull f2_fma(ull a, ull b, ull c) {
    ull d; asm("fma.rn.f32x2 %0,%1,%2,%3;" : "=l"(d) : "l"(a), "l"(b), "l"(c)); return d;
}
__device__ __forceinline__ ull f2_mul(ull a, ull b) {
    ull d; asm("mul.rn.f32x2 %0,%1,%2;" : "=l"(d) : "l"(a), "l"(b)); return d;
}

__device__ float g_partial[NBF];
__device__ float g_xtscale[BDIM];
__device__ float g_qscale[BDIM];

// 28 strict upper-triangle pairs (m < n)
__constant__ unsigned char c_pm[28] = {
    0,0,0,0,0,0,0,
    1,1,1,1,1,1,
    2,2,2,2,2,
    3,3,3,3,
    4,4,4,
    5,5,
    6};
__constant__ unsigned char c_pn[28] = {
    1,2,3,4,5,6,7,
    2,3,4,5,6,7,
    3,4,5,6,7,
    4,5,6,7,
    5,6,7,
    6,7,
    7};

__global__ __launch_bounds__(NTHREADS, 4)
void iss_main(const float* __restrict__ r,
              const float* __restrict__ Qr,
              const float* __restrict__ Qi,
              const float* __restrict__ xr,
              const float* __restrict__ xi,
              float* __restrict__ out)
{
    extern __shared__ float sm[];
    float*  sxr  = sm + OFF_SXR;
    float*  sxi  = sm + OFF_SXI;
    float*  sr   = sm + OFF_SR;
    float2* part = (float2*)(sm + OFF_PART);  // [slot][k][chunk], aliases sr
    float2* V    = (float2*)(sm + OFF_V);     // [k][m][n]
    float2* sQ   = (float2*)(sm + OFF_SQ);    // [k][m]
    ulonglong2* sQp = (ulonglong2*)(sm + OFF_SQP); // [m][n] packed {(x,x),(y,y)}
    float*  red  = sm + OFF_RED;

    const int tid = threadIdx.x;
    const int bf = blockIdx.x;
    const size_t base = (size_t)bf * (MDIM * TDIM);

    // ---- stage inputs in SMEM via float4 (r clipped at load) ----
    {
        const float4* xr4 = (const float4*)(xr + base);
        const float4* xi4 = (const float4*)(xi + base);
        const float4* r4  = (const float4*)(r + base);
        for (int i = tid; i < MDIM * TDIM / 4; i += NTHREADS) {
            int m = i >> 7, t4 = (i & 127) << 2;
            float4 a = xr4[i];
            *(float4*)(sxr + m * XS + t4) = a;
            float4 b = xi4[i];
            *(float4*)(sxi + m * XS + t4) = b;
            float4 c = r4[i];
            c.x = fmaxf(c.x, 1e-3f); c.y = fmaxf(c.y, 1e-3f);
            c.z = fmaxf(c.z, 1e-3f); c.w = fmaxf(c.w, 1e-3f);
            *(float4*)(sr + m * XS + t4) = c;
        }
    }
    if (tid < 64) {
        sQ[tid] = make_float2(Qr[(size_t)bf * 64 + tid], Qi[(size_t)bf * 64 + tid]);
    }
    __syncthreads();

    // ---- V accumulation. warp == chunk (64 t's). slot = lane. ----
    ull accx[8], accy[8];
    {
        const int chunk = tid >> 5;
        const int slot  = tid & 31;
        const bool offd = slot < 28;
        int m, n;
        if (offd) { m = c_pm[slot]; n = c_pn[slot]; }
        else      { m = slot - 28;  n = slot - 24; }
        const ulonglong2* pxrm = (const ulonglong2*)(sxr + m * XS + chunk * 64);
        const ulonglong2* pxim = (const ulonglong2*)(sxi + m * XS + chunk * 64);
        const ulonglong2* pxrn = (const ulonglong2*)(sxr + n * XS + chunk * 64);
        const ulonglong2* pxin = (const ulonglong2*)(sxi + n * XS + chunk * 64);
        const float* srl = sr + chunk * 64;

        #pragma unroll
        for (int k = 0; k < 8; k++) { accx[k] = 0ULL; accy[k] = 0ULL; }

        #pragma unroll 2
        for (int q = 0; q < 16; q++) {            // q indexes groups of 4 t's
            ulonglong2 vrm = pxrm[q];
            ulonglong2 vim = pxim[q];
            ulonglong2 vrn = pxrn[q];
            ulonglong2 vin = pxin[q];
            ull a01, a23, b01, b23;
            if (offd) {
                a01 = f2_fma(vrm.x, vrn.x, f2_mul(vim.x, vin.x));
                a23 = f2_fma(vrm.y, vrn.y, f2_mul(vim.y, vin.y));
                b01 = f2_fma(vim.x, vrn.x, f2_mul(vrm.x ^ SGN2, vin.x));
                b23 = f2_fma(vim.y, vrn.y, f2_mul(vrm.y ^ SGN2, vin.y));
            } else {
                a01 = f2_fma(vrm.x, vrm.x, f2_mul(vim.x, vim.x));
                a23 = f2_fma(vrm.y, vrm.y, f2_mul(vim.y, vim.y));
                b01 = f2_fma(vrn.x, vrn.x, f2_mul(vin.x, vin.x));
                b23 = f2_fma(vrn.y, vrn.y, f2_mul(vin.y, vin.y));
            }
            #pragma unroll
            for (int k = 0; k < 8; k++) {
                ulonglong2 rk = *(const ulonglong2*)(srl + k * XS + q * 4);
                accx[k] = f2_fma(rk.x, a01, accx[k]);
                accx[k] = f2_fma(rk.y, a23, accx[k]);
                accy[k] = f2_fma(rk.x, b01, accy[k]);
                accy[k] = f2_fma(rk.y, b23, accy[k]);
            }
        }
    }
    __syncthreads();   // all sr reads complete before part (aliased) is written

    {
        const int chunk = tid >> 5;
        const int slot  = tid & 31;
        #pragma unroll
        for (int k = 0; k < 8; k++) {
            float xl, xh, yl, yh;
            f2_unpack(accx[k], xl, xh);
            f2_unpack(accy[k], yl, yh);
            part[(slot * 8 + k) * 8 + chunk] = make_float2(xl + xh, yl + yh);
        }
    }
    __syncthreads();

    // reduce over chunks, fill V. 32 slots * 8 k = 256 items exactly.
    {
        int slot = tid >> 3, k = tid & 7;
        float2 s = make_float2(0.f, 0.f);
        #pragma unroll
        for (int c = 0; c < 8; c++) {
            float2 p = part[(slot * 8 + k) * 8 + c];
            s.x += p.x; s.y += p.y;
        }
        s.x *= (1.0f / TDIM);
        s.y *= (1.0f / TDIM);
        if (slot < 28) {
            int m = c_pm[slot], n = c_pn[slot];
            V[(k * 8 + m) * 8 + n] = s;
            V[(k * 8 + n) * 8 + m] = make_float2(s.x, -s.y);
        } else {
            int d = slot - 28;
            V[(k * 8 + d) * 8 + d]           = make_float2(s.x, 0.f);
            V[(k * 8 + d + 4) * 8 + d + 4]   = make_float2(s.y, 0.f);
        }
    }
    __syncthreads();

    // trV + diagonal regularization
    if (tid < 8) {
        int k = tid;
        float tr = 0.f;
        #pragma unroll
        for (int m = 0; m < 8; m++) tr += V[(k * 8 + m) * 8 + m].x;
        float reg = fmaxf(tr, 1.0f) * 1e-6f;
        #pragma unroll
        for (int m = 0; m < 8; m++) V[(k * 8 + m) * 8 + m].x += reg;
    }
    __syncthreads();

    // ---- 2 x 8 sweep, fully register-resident on warp 0 ----
    if (tid < 32) {
        const int lane = tid;
        const int kp = lane >> 2;
        const int j  = lane & 3;
        const int m0 = 2 * j, m1 = 2 * j + 1;

        float2 Vr0[8], Vr1[8];
        #pragma unroll
        for (int n = 0; n < 8; n++) {
            Vr0[n] = V[(kp * 8 + m0) * 8 + n];
            Vr1[n] = V[(kp * 8 + m1) * 8 + n];
        }
        float2 Q0 = sQ[kp * 8 + m0];
        float2 Q1 = sQ[kp * 8 + m1];

        #pragma unroll 1
        for (int it = 0; it < 2; it++) {
            #pragma unroll 1
            for (int k = 0; k < 8; k++) {
                float qr[8], qi[8];
                #pragma unroll
                for (int jp = 0; jp < 4; jp++) {
                    int src = k * 4 + jp;
                    qr[2 * jp]     = __shfl_sync(0xffffffffu, Q0.x, src);
                    qi[2 * jp]     = __shfl_sync(0xffffffffu, Q0.y, src);
                    qr[2 * jp + 1] = __shfl_sync(0xffffffffu, Q1.x, src);
                    qi[2 * jp + 1] = __shfl_sync(0xffffffffu, Q1.y, src);
                }
                float vq0r = 0.f, vq0i = 0.f, vq1r = 0.f, vq1i = 0.f;
                #pragma unroll
                for (int n = 0; n < 8; n++) {
                    vq0r += Vr0[n].x * qr[n] + Vr0[n].y * qi[n];
                    vq0i += Vr0[n].y * qr[n] - Vr0[n].x * qi[n];
                    vq1r += Vr1[n].x * qr[n] + Vr1[n].y * qi[n];
                    vq1i += Vr1[n].y * qr[n] - Vr1[n].x * qi[n];
                }
                float pq  = qr[m0] * vq0r - qi[m0] * vq0i
                          + qr[m1] * vq1r - qi[m1] * vq1i;
                float pnr = Q0.x * vq0r - Q0.y * vq0i
                          + Q1.x * vq1r - Q1.y * vq1i;
                float pni = Q0.x * vq0i + Q0.y * vq0r
                          + Q1.x * vq1i + Q1.y * vq1r;
                pq  += __shfl_xor_sync(0xffffffffu, pq, 1);
                pnr += __shfl_xor_sync(0xffffffffu, pnr, 1);
                pni += __shfl_xor_sync(0xffffffffu, pni, 1);
                pq  += __shfl_xor_sync(0xffffffffu, pq, 2);
                pnr += __shfl_xor_sync(0xffffffffu, pnr, 2);
                pni += __shfl_xor_sync(0xffffffffu, pni, 2);

                float qv = fmaxf(pq, 1e-6f);
                float vrr, vii;
                if (kp == k) {
                    vrr = 1.0f - __frsqrt_rn(qv);
                    vii = 0.0f;
                } else {
                    float inv = __fdividef(1.0f, qv);
                    vrr = pnr * inv;
                    vii = pni * inv;
                }
                Q0.x -= vrr * qr[m0] - vii * qi[m0];
                Q0.y -= vrr * qi[m0] + vii * qr[m0];
                Q1.x -= vrr * qr[m1] - vii * qi[m1];
                Q1.y -= vrr * qi[m1] + vii * qr[m1];
            }
        }
        sQ[kp * 8 + m0] = Q0;
        sQ[kp * 8 + m1] = Q1;
        // packed Q for the Qx phase: sQp[row=kp][col=m] = {(x,x),(y,y)}
        sQp[kp * 8 + m0] = make_ulonglong2(f2_pack(Q0.x, Q0.x), f2_pack(Q0.y, Q0.y));
        sQp[kp * 8 + m1] = make_ulonglong2(f2_pack(Q1.x, Q1.x), f2_pack(Q1.y, Q1.y));
    }
    __syncthreads();

    // ---- Qx = Q @ x ; xt = |Qx|^2. Transposed decomposition:
    // warp = t-chunk (64 t), lane = 2 consecutive t's; all 8 m in registers.
    // x read ONCE from SMEM per warp; Q via 1-wavefront broadcast LDS.128.
    float local = 0.f;
    float* out_xt = out + QELEMS + base;
    {
        const int chunk = tid >> 5;
        const int lane = tid & 31;
        const int t = chunk * 64 + lane * 2;

        ull arP[8], aiP[8];
        #pragma unroll
        for (int m = 0; m < 8; m++) { arP[m] = 0ULL; aiP[m] = 0ULL; }

        #pragma unroll
        for (int n = 0; n < 8; n++) {
            ull vr  = *(const ull*)(sxr + n * XS + t);
            ull vi  = *(const ull*)(sxi + n * XS + t);
            ull vin = vi ^ SGN2;      // -xi for the ar accumulation
            #pragma unroll
            for (int m = 0; m < 8; m++) {
                ulonglong2 qp = sQp[m * 8 + n];    // broadcast LDS.128 (1 wf)
                arP[m] = f2_fma(qp.x, vr, f2_fma(qp.y, vin, arP[m]));
                aiP[m] = f2_fma(qp.x, vi, f2_fma(qp.y, vr,  aiP[m]));
            }
        }
        #pragma unroll
        for (int m = 0; m < 8; m++) {
            float r0, r1, i0, i1;
            f2_unpack(arP[m], r0, r1);
            f2_unpack(aiP[m], i0, i1);
            float v0 = r0 * r0 + i0 * i0;
            float v1 = r1 * r1 + i1 * i1;
            local += v0 + v1;
            *(float2*)(out_xt + m * TDIM + t) = make_float2(v0, v1);
        }
    }
    // write unnormalized Q (real part only — output buffer is float32)
    if (tid < 64) {
        out[(size_t)bf * 64 + tid] = sQ[tid].x;
    }
    // deterministic block reduction: warp shfl tree -> 8 partials -> warp 0
    {
        #pragma unroll
        for (int d = 16; d > 0; d >>= 1)
            local += __shfl_xor_sync(0xffffffffu, local, d);
        if ((tid & 31) == 0) red[tid >> 5] = local;
    }
    __syncthreads();
    if (tid < 32) {
        float s = (tid < 8) ? red[tid] : 0.f;
        #pragma unroll
        for (int d = 4; d > 0; d >>= 1)
            s += __shfl_xor_sync(0xffffffffu, s, d);
        if (tid == 0) g_partial[bf] = s;
    }
}

__global__ void iss_reduce()
{
    __shared__ float red[256];
    int b = blockIdx.x, tid = threadIdx.x;
    float s = 0.f;
    for (int i = tid; i < FDIM; i += 256) s += g_partial[b * FDIM + i];
    red[tid] = s;
    __syncthreads();
    for (int st = 128; st > 0; st >>= 1) {
        if (tid < st) red[tid] += red[tid + st];
        __syncthreads();
    }
    if (tid == 0) {
        float scale = red[0] / (float)PER_B_XT;
        g_xtscale[b] = 1.0f / scale;
        g_qscale[b]  = 1.0f / sqrtf(fmaxf(scale, 1e-6f));
    }
}

// single normalization pass over the whole output buffer (float4)
__global__ void iss_norm(float4* __restrict__ outv)
{
    size_t idx = (size_t)blockIdx.x * blockDim.x + threadIdx.x;
    if (idx >= (size_t)TOTAL4) return;
    float s;
    if (idx < (size_t)Q4) {
        s = g_qscale[(int)(idx / (PER_B_QE / 4))];
    } else {
        s = g_xtscale[(int)((idx - Q4) / (PER_B_XT / 4))];
    }
    float4 v = outv[idx];
    v.x *= s; v.y *= s; v.z *= s; v.w *= s;
    outv[idx] = v;
}

extern "C" void kernel_launch(void* const* d_in, const int* in_sizes, int n_in,
                              void* d_out, int out_size)
{
    const float* r  = (const float*)d_in[0];
    const float* Qr = (const float*)d_in[1];
    const float* Qi = (const float*)d_in[2];
    const float* xr = (const float*)d_in[3];
    const float* xi = (const float*)d_in[4];
    float* out = (float*)d_out;

    cudaFuncSetAttribute(iss_main, cudaFuncAttributeMaxDynamicSharedMemorySize, SMEM_BYTES);

    iss_main<<<NBF, NTHREADS, SMEM_BYTES>>>(r, Qr, Qi, xr, xi, out);
    iss_reduce<<<BDIM, 256>>>();
    iss_norm<<<(TOTAL4 + 255) / 256, 256>>>((float4*)out);
}

// round 10
// speedup vs baseline: 1.5437x; 1.1712x over previous
#include <cuda_runtime.h>
#include <math.h>

#define BDIM 8
#define FDIM 1025
#define MDIM 8
#define TDIM 512
#define NBF (BDIM * FDIM)            // 8200
#define NTHREADS 256
#define XS 516                        // padded SMEM row stride (16B-aligned rows)

#define QELEMS (NBF * MDIM * MDIM)           // 524,800  (Q stored as real part only)
#define XTCOUNT (NBF * MDIM * TDIM)          // 33,587,200
#define PER_B_XT (FDIM * MDIM * TDIM)        // 4,198,400
#define PER_B_QE (FDIM * MDIM * MDIM)        // 65,600
#define TOTAL4 ((QELEMS + XTCOUNT) / 4)      // 8,528,000 float4s
#define Q4 (QELEMS / 4)                      // 131,200

// part layout: float2 addr = slot*66 + k + chunk*8  (bank-conflict-tuned)
#define PART_SLOT_STRIDE 66
#define PART_FLOATS (32 * PART_SLOT_STRIDE * 2)   // 4224 floats

// SMEM layout (float offsets). part ALIASES sr (r dead after V-accum) + 96 extra.
#define OFF_SXR 0
#define OFF_SXI (OFF_SXR + MDIM * XS)        // 4128
#define OFF_SR  (OFF_SXI + MDIM * XS)        // 8256  (4128 floats)
#define OFF_PART OFF_SR                      // 4224 floats, aliased+extended
#define OFF_V   (OFF_PART + PART_FLOATS)     // 12480 (512 float2)
#define OFF_SQ  (OFF_V + 1024)               // 13504 (64 float2)
#define OFF_SQP (OFF_SQ + 128)               // 13632 (64 ulonglong2 = 256 floats)
#define OFF_RED (OFF_SQP + 256)              // 13888 (8 floats)
#define SMEM_FLOATS (OFF_RED + 8)            // 13896
#define SMEM_BYTES (SMEM_FLOATS * 4)         // 55,584 B -> 4 blocks/SM

typedef unsigned long long ull;
#define SGN2 0x8000000080000000ULL

__device__ __forceinline__ ull f2_pack(float lo, float hi) {
    ull r; asm("mov.b64 %0,{%1,%2};" : "=l"(r) : "f"(lo), "f"(hi)); return r;
}
__device__ __forceinline__ void f2_unpack(ull v, float& lo, float& hi) {
    asm("mov.b64 {%0,%1},%2;" : "=f"(lo), "=f"(hi) : "l"(v));
}
__device__ __forceinline__ ull f2_fma(ull a, ull b, ull c) {
    ull d; asm("fma.rn.f32x2 %0,%1,%2,%3;" : "=l"(d) : "l"(a), "l"(b), "l"(c)); return d;
}
__device__ __forceinline__ ull f2_mul(ull a, ull b) {
    ull d; asm("mul.rn.f32x2 %0,%1,%2;" : "=l"(d) : "l"(a), "l"(b)); return d;
}

__device__ float g_partial[NBF];
__device__ float g_xtscale[BDIM];
__device__ float g_qscale[BDIM];

// 28 strict upper-triangle pairs (m < n)
__constant__ unsigned char c_pm[28] = {
    0,0,0,0,0,0,0,
    1,1,1,1,1,1,
    2,2,2,2,2,
    3,3,3,3,
    4,4,4,
    5,5,
    6};
__constant__ unsigned char c_pn[28] = {
    1,2,3,4,5,6,7,
    2,3,4,5,6,7,
    3,4,5,6,7,
    4,5,6,7,
    5,6,7,
    6,7,
    7};

__global__ __launch_bounds__(NTHREADS, 4)
void iss_main(const float* __restrict__ r,
              const float* __restrict__ Qr,
              const float* __restrict__ Qi,
              const float* __restrict__ xr,
              const float* __restrict__ xi,
              float* __restrict__ out)
{
    extern __shared__ float sm[];
    float*  sxr  = sm + OFF_SXR;
    float*  sxi  = sm + OFF_SXI;
    float*  sr   = sm + OFF_SR;
    float2* part = (float2*)(sm + OFF_PART);  // addr = slot*66 + k + chunk*8
    float2* V    = (float2*)(sm + OFF_V);     // [k][m][n]
    float2* sQ   = (float2*)(sm + OFF_SQ);    // [k][m]
    ulonglong2* sQp = (ulonglong2*)(sm + OFF_SQP); // [m][n] packed {(x,x),(y,y)}
    float*  red  = sm + OFF_RED;

    const int tid = threadIdx.x;
    const int bf = blockIdx.x;
    const size_t base = (size_t)bf * (MDIM * TDIM);

    // ---- stage inputs in SMEM via float4 (r clipped at load) ----
    {
        const float4* xr4 = (const float4*)(xr + base);
        const float4* xi4 = (const float4*)(xi + base);
        const float4* r4  = (const float4*)(r + base);
        for (int i = tid; i < MDIM * TDIM / 4; i += NTHREADS) {
            int m = i >> 7, t4 = (i & 127) << 2;
            float4 a = xr4[i];
            *(float4*)(sxr + m * XS + t4) = a;
            float4 b = xi4[i];
            *(float4*)(sxi + m * XS + t4) = b;
            float4 c = r4[i];
            c.x = fmaxf(c.x, 1e-3f); c.y = fmaxf(c.y, 1e-3f);
            c.z = fmaxf(c.z, 1e-3f); c.w = fmaxf(c.w, 1e-3f);
            *(float4*)(sr + m * XS + t4) = c;
        }
    }
    if (tid < 64) {
        sQ[tid] = make_float2(Qr[(size_t)bf * 64 + tid], Qi[(size_t)bf * 64 + tid]);
    }
    __syncthreads();

    // ---- V accumulation. warp == chunk (64 t's). slot = lane. ----
    ull accx[8], accy[8];
    {
        const int chunk = tid >> 5;
        const int slot  = tid & 31;
        const bool offd = slot < 28;
        int m, n;
        if (offd) { m = c_pm[slot]; n = c_pn[slot]; }
        else      { m = slot - 28;  n = slot - 24; }
        const ulonglong2* pxrm = (const ulonglong2*)(sxr + m * XS + chunk * 64);
        const ulonglong2* pxim = (const ulonglong2*)(sxi + m * XS + chunk * 64);
        const ulonglong2* pxrn = (const ulonglong2*)(sxr + n * XS + chunk * 64);
        const ulonglong2* pxin = (const ulonglong2*)(sxi + n * XS + chunk * 64);
        const float* srl = sr + chunk * 64;

        #pragma unroll
        for (int k = 0; k < 8; k++) { accx[k] = 0ULL; accy[k] = 0ULL; }

        #pragma unroll 2
        for (int q = 0; q < 16; q++) {            // q indexes groups of 4 t's
            ulonglong2 vrm = pxrm[q];
            ulonglong2 vim = pxim[q];
            ulonglong2 vrn = pxrn[q];
            ulonglong2 vin = pxin[q];
            ull a01, a23, b01, b23;
            if (offd) {
                a01 = f2_fma(vrm.x, vrn.x, f2_mul(vim.x, vin.x));
                a23 = f2_fma(vrm.y, vrn.y, f2_mul(vim.y, vin.y));
                b01 = f2_fma(vim.x, vrn.x, f2_mul(vrm.x ^ SGN2, vin.x));
                b23 = f2_fma(vim.y, vrn.y, f2_mul(vrm.y ^ SGN2, vin.y));
            } else {
                a01 = f2_fma(vrm.x, vrm.x, f2_mul(vim.x, vim.x));
                a23 = f2_fma(vrm.y, vrm.y, f2_mul(vim.y, vim.y));
                b01 = f2_fma(vrn.x, vrn.x, f2_mul(vin.x, vin.x));
                b23 = f2_fma(vrn.y, vrn.y, f2_mul(vin.y, vin.y));
            }
            #pragma unroll
            for (int k = 0; k < 8; k++) {
                ulonglong2 rk = *(const ulonglong2*)(srl + k * XS + q * 4);
                accx[k] = f2_fma(rk.x, a01, accx[k]);
                accx[k] = f2_fma(rk.y, a23, accx[k]);
                accy[k] = f2_fma(rk.x, b01, accy[k]);
                accy[k] = f2_fma(rk.y, b23, accy[k]);
            }
        }
    }
    __syncthreads();   // all sr reads complete before part (aliased) is written

    // write partials: 4x STS.128, conflict-free (slot stride 66 f2 = 528B)
    {
        const int chunk = tid >> 5;
        const int slot  = tid & 31;
        ull* prow = (ull*)(part + slot * PART_SLOT_STRIDE + chunk * 8);
        #pragma unroll
        for (int kp = 0; kp < 4; kp++) {
            float x0l, x0h, y0l, y0h, x1l, x1h, y1l, y1h;
            f2_unpack(accx[2 * kp],     x0l, x0h);
            f2_unpack(accy[2 * kp],     y0l, y0h);
            f2_unpack(accx[2 * kp + 1], x1l, x1h);
            f2_unpack(accy[2 * kp + 1], y1l, y1h);
            ulonglong2 w;
            w.x = f2_pack(x0l + x0h, y0l + y0h);   // float2 for k=2kp
            w.y = f2_pack(x1l + x1h, y1l + y1h);   // float2 for k=2kp+1
            *(ulonglong2*)(prow + 2 * kp) = w;
        }
    }
    __syncthreads();

    // reduce over chunks, fill V. warp = k (tid>>5), lane = slot. 2-way max.
    {
        int slot = tid & 31, k = tid >> 5;
        const float2* prow = part + slot * PART_SLOT_STRIDE + k;
        float2 s = make_float2(0.f, 0.f);
        #pragma unroll
        for (int c = 0; c < 8; c++) {
            float2 p = prow[c * 8];
            s.x += p.x; s.y += p.y;
        }
        s.x *= (1.0f / TDIM);
        s.y *= (1.0f / TDIM);
        if (slot < 28) {
            int m = c_pm[slot], n = c_pn[slot];
            V[(k * 8 + m) * 8 + n] = s;
            V[(k * 8 + n) * 8 + m] = make_float2(s.x, -s.y);
        } else {
            int d = slot - 28;
            V[(k * 8 + d) * 8 + d]           = make_float2(s.x, 0.f);
            V[(k * 8 + d + 4) * 8 + d + 4]   = make_float2(s.y, 0.f);
        }
    }
    __syncthreads();

    // trV + diagonal regularization
    if (tid < 8) {
        int k = tid;
        float tr = 0.f;
        #pragma unroll
        for (int m = 0; m < 8; m++) tr += V[(k * 8 + m) * 8 + m].x;
        float reg = fmaxf(tr, 1.0f) * 1e-6f;
        #pragma unroll
        for (int m = 0; m < 8; m++) V[(k * 8 + m) * 8 + m].x += reg;
    }
    __syncthreads();

    // ---- 2 x 8 sweep, fully register-resident on warp 0 ----
    if (tid < 32) {
        const int lane = tid;
        const int kp = lane >> 2;
        const int j  = lane & 3;
        const int m0 = 2 * j, m1 = 2 * j + 1;

        float2 Vr0[8], Vr1[8];
        #pragma unroll
        for (int n = 0; n < 8; n++) {
            Vr0[n] = V[(kp * 8 + m0) * 8 + n];
            Vr1[n] = V[(kp * 8 + m1) * 8 + n];
        }
        float2 Q0 = sQ[kp * 8 + m0];
        float2 Q1 = sQ[kp * 8 + m1];

        #pragma unroll 1
        for (int it = 0; it < 2; it++) {
            #pragma unroll 1
            for (int k = 0; k < 8; k++) {
                float qr[8], qi[8];
                #pragma unroll
                for (int jp = 0; jp < 4; jp++) {
                    int src = k * 4 + jp;
                    qr[2 * jp]     = __shfl_sync(0xffffffffu, Q0.x, src);
                    qi[2 * jp]     = __shfl_sync(0xffffffffu, Q0.y, src);
                    qr[2 * jp + 1] = __shfl_sync(0xffffffffu, Q1.x, src);
                    qi[2 * jp + 1] = __shfl_sync(0xffffffffu, Q1.y, src);
                }
                float vq0r = 0.f, vq0i = 0.f, vq1r = 0.f, vq1i = 0.f;
                #pragma unroll
                for (int n = 0; n < 8; n++) {
                    vq0r += Vr0[n].x * qr[n] + Vr0[n].y * qi[n];
                    vq0i += Vr0[n].y * qr[n] - Vr0[n].x * qi[n];
                    vq1r += Vr1[n].x * qr[n] + Vr1[n].y * qi[n];
                    vq1i += Vr1[n].y * qr[n] - Vr1[n].x * qi[n];
                }
                float pq  = qr[m0] * vq0r - qi[m0] * vq0i
                          + qr[m1] * vq1r - qi[m1] * vq1i;
                float pnr = Q0.x * vq0r - Q0.y * vq0i
                          + Q1.x * vq1r - Q1.y * vq1i;
                float pni = Q0.x * vq0i + Q0.y * vq0r
                          + Q1.x * vq1i + Q1.y * vq1r;
                pq  += __shfl_xor_sync(0xffffffffu, pq, 1);
                pnr += __shfl_xor_sync(0xffffffffu, pnr, 1);
                pni += __shfl_xor_sync(0xffffffffu, pni, 1);
                pq  += __shfl_xor_sync(0xffffffffu, pq, 2);
                pnr += __shfl_xor_sync(0xffffffffu, pnr, 2);
                pni += __shfl_xor_sync(0xffffffffu, pni, 2);

                float qv = fmaxf(pq, 1e-6f);
                float vrr, vii;
                if (kp == k) {
                    vrr = 1.0f - __frsqrt_rn(qv);
                    vii = 0.0f;
                } else {
                    float inv = __fdividef(1.0f, qv);
                    vrr = pnr * inv;
                    vii = pni * inv;
                }
                Q0.x -= vrr * qr[m0] - vii * qi[m0];
                Q0.y -= vrr * qi[m0] + vii * qr[m0];
                Q1.x -= vrr * qr[m1] - vii * qi[m1];
                Q1.y -= vrr * qi[m1] + vii * qr[m1];
            }
        }
        sQ[kp * 8 + m0] = Q0;
        sQ[kp * 8 + m1] = Q1;
        // packed Q for the Qx phase: sQp[row=kp][col=m] = {(x,x),(y,y)}
        sQp[kp * 8 + m0] = make_ulonglong2(f2_pack(Q0.x, Q0.x), f2_pack(Q0.y, Q0.y));
        sQp[kp * 8 + m1] = make_ulonglong2(f2_pack(Q1.x, Q1.x), f2_pack(Q1.y, Q1.y));
    }
    __syncthreads();

    // ---- Qx = Q @ x ; xt = |Qx|^2. warp = t-chunk, lane = 2 t's; 8 m in regs.
    float local = 0.f;
    float* out_xt = out + QELEMS + base;
    {
        const int chunk = tid >> 5;
        const int lane = tid & 31;
        const int t = chunk * 64 + lane * 2;

        ull arP[8], aiP[8];
        #pragma unroll
        for (int m = 0; m < 8; m++) { arP[m] = 0ULL; aiP[m] = 0ULL; }

        #pragma unroll
        for (int n = 0; n < 8; n++) {
            ull vr  = *(const ull*)(sxr + n * XS + t);
            ull vi  = *(const ull*)(sxi + n * XS + t);
            ull vin = vi ^ SGN2;      // -xi for the ar accumulation
            #pragma unroll
            for (int m = 0; m < 8; m++) {
                ulonglong2 qp = sQp[m * 8 + n];    // broadcast LDS.128 (1 wf)
                arP[m] = f2_fma(qp.x, vr, f2_fma(qp.y, vin, arP[m]));
                aiP[m] = f2_fma(qp.x, vi, f2_fma(qp.y, vr,  aiP[m]));
            }
        }
        #pragma unroll
        for (int m = 0; m < 8; m++) {
            float r0, r1, i0, i1;
            f2_unpack(arP[m], r0, r1);
            f2_unpack(aiP[m], i0, i1);
            float v0 = r0 * r0 + i0 * i0;
            float v1 = r1 * r1 + i1 * i1;
            local += v0 + v1;
            *(float2*)(out_xt + m * TDIM + t) = make_float2(v0, v1);
        }
    }
    // write unnormalized Q (real part only — output buffer is float32)
    if (tid < 64) {
        out[(size_t)bf * 64 + tid] = sQ[tid].x;
    }
    // deterministic block reduction: warp shfl tree -> 8 partials -> warp 0
    {
        #pragma unroll
        for (int d = 16; d > 0; d >>= 1)
            local += __shfl_xor_sync(0xffffffffu, local, d);
        if ((tid & 31) == 0) red[tid >> 5] = local;
    }
    __syncthreads();
    if (tid < 32) {
        float s = (tid < 8) ? red[tid] : 0.f;
        #pragma unroll
        for (int d = 4; d > 0; d >>= 1)
            s += __shfl_xor_sync(0xffffffffu, s, d);
        if (tid == 0) g_partial[bf] = s;
    }
}

__global__ void iss_reduce()
{
    __shared__ float red[256];
    int b = blockIdx.x, tid = threadIdx.x;
    float s = 0.f;
    for (int i = tid; i < FDIM; i += 256) s += g_partial[b * FDIM + i];
    red[tid] = s;
    __syncthreads();
    for (int st = 128; st > 0; st >>= 1) {
        if (tid < st) red[tid] += red[tid + st];
        __syncthreads();
    }
    if (tid == 0) {
        float scale = red[0] / (float)PER_B_XT;
        g_xtscale[b] = 1.0f / scale;
        g_qscale[b]  = 1.0f / sqrtf(fmaxf(scale, 1e-6f));
    }
}

// single normalization pass over the whole output buffer (float4)
__global__ void iss_norm(float4* __restrict__ outv)
{
    size_t idx = (size_t)blockIdx.x * blockDim.x + threadIdx.x;
    if (idx >= (size_t)TOTAL4) return;
    float s;
    if (idx < (size_t)Q4) {
        s = g_qscale[(int)(idx / (PER_B_QE / 4))];
    } else {
        s = g_xtscale[(int)((idx - Q4) / (PER_B_XT / 4))];
    }
    float4 v = outv[idx];
    v.x *= s; v.y *= s; v.z *= s; v.w *= s;
    outv[idx] = v;
}

extern "C" void kernel_launch(void* const* d_in, const int* in_sizes, int n_in,
                              void* d_out, int out_size)
{
    const float* r  = (const float*)d_in[0];
    const float* Qr = (const float*)d_in[1];
    const float* Qi = (const float*)d_in[2];
    const float* xr = (const float*)d_in[3];
    const float* xi = (const float*)d_in[4];
    float* out = (float*)d_out;

    cudaFuncSetAttribute(iss_main, cudaFuncAttributeMaxDynamicSharedMemorySize, SMEM_BYTES);

    iss_main<<<NBF, NTHREADS, SMEM_BYTES>>>(r, Qr, Qi, xr, xi, out);
    iss_reduce<<<BDIM, 256>>>();
    iss_norm<<<(TOTAL4 + 255) / 256, 256>>>((float4*)out);
}

// round 13
// speedup vs baseline: 1.5865x; 1.0277x over previous
#include <cuda_runtime.h>
#include <math.h>

#define BDIM 8
#define FDIM 1025
#define MDIM 8
#define TDIM 512
#define NBF (BDIM * FDIM)            // 8200
#define NTHREADS 256
#define XS 516                        // padded SMEM row stride (16B-aligned rows)

#define QELEMS (NBF * MDIM * MDIM)           // 524,800  (Q stored as real part only)
#define XTCOUNT (NBF * MDIM * TDIM)          // 33,587,200
#define PER_B_XT (FDIM * MDIM * TDIM)        // 4,198,400
#define PER_B_QE (FDIM * MDIM * MDIM)        // 65,600
#define TOTAL4 ((QELEMS + XTCOUNT) / 4)      // 8,528,000 float4s
#define Q4 (QELEMS / 4)                      // 131,200

// part layout: float2 addr = slot*66 + k + chunk*8  (bank-conflict-tuned)
#define PART_SLOT_STRIDE 66
#define PART_FLOATS (32 * PART_SLOT_STRIDE * 2)   // 4224 floats

// SMEM layout (float offsets). part ALIASES sr (r dead after V-accum) + 96 extra.
#define OFF_SXR 0
#define OFF_SXI (OFF_SXR + MDIM * XS)        // 4128
#define OFF_SR  (OFF_SXI + MDIM * XS)        // 8256  (4128 floats)
#define OFF_PART OFF_SR                      // 4224 floats, aliased+extended
#define OFF_V   (OFF_PART + PART_FLOATS)     // 12480 (512 float2)
#define OFF_SQ  (OFF_V + 1024)               // 13504 (64 float2)
#define OFF_SQP (OFF_SQ + 128)               // 13632 (64 ulonglong2 = 256 floats)
#define OFF_RED (OFF_SQP + 256)              // 13888 (8 floats)
#define SMEM_FLOATS (OFF_RED + 8)            // 13896
#define SMEM_BYTES (SMEM_FLOATS * 4)         // 55,584 B -> 4 blocks/SM

typedef unsigned long long ull;
#define SGN2 0x8000000080000000ULL

__device__ __forceinline__ ull f2_pack(float lo, float hi) {
    ull r; asm("mov.b64 %0,{%1,%2};" : "=l"(r) : "f"(lo), "f"(hi)); return r;
}
__device__ __forceinline__ void f2_unpack(ull v, float& lo, float& hi) {
    asm("mov.b64 {%0,%1},%2;" : "=f"(lo), "=f"(hi) : "l"(v));
}
__device__ __forceinline__ ull f2_fma(ull a, ull b, ull c) {
    ull d; asm("fma.rn.f32x2 %0,%1,%2,%3;" : "=l"(d) : "l"(a), "l"(b), "l"(c)); return d;
}
__device__ __forceinline__ ull f2_mul(ull a, ull b) {
    ull d; asm("mul.rn.f32x2 %0,%1,%2;" : "=l"(d) : "l"(a), "l"(b)); return d;
}

__device__ float g_partial[NBF];
__device__ float g_xtscale[BDIM];
__device__ float g_qscale[BDIM];

// 28 strict upper-triangle pairs (m < n)
__constant__ unsigned char c_pm[28] = {
    0,0,0,0,0,0,0,
    1,1,1,1,1,1,
    2,2,2,2,2,
    3,3,3,3,
    4,4,4,
    5,5,
    6};
__constant__ unsigned char c_pn[28] = {
    1,2,3,4,5,6,7,
    2,3,4,5,6,7,
    3,4,5,6,7,
    4,5,6,7,
    5,6,7,
    6,7,
    7};

__global__ __launch_bounds__(NTHREADS, 4)
void iss_main(const float* __restrict__ r,
              const float* __restrict__ Qr,
              const float* __restrict__ Qi,
              const float* __restrict__ xr,
              const float* __restrict__ xi,
              float* __restrict__ out)
{
    extern __shared__ float sm[];
    float*  sxr  = sm + OFF_SXR;
    float*  sxi  = sm + OFF_SXI;
    float*  sr   = sm + OFF_SR;
    float2* part = (float2*)(sm + OFF_PART);  // addr = slot*66 + k + chunk*8
    float2* V    = (float2*)(sm + OFF_V);     // [k][m][n]
    float2* sQ   = (float2*)(sm + OFF_SQ);    // [k][m]
    ulonglong2* sQp = (ulonglong2*)(sm + OFF_SQP); // [m][n] packed {(x,x),(y,y)}
    float*  red  = sm + OFF_RED;

    const int tid = threadIdx.x;
    const int bf = blockIdx.x;
    const size_t base = (size_t)bf * (MDIM * TDIM);

    // ---- stage inputs in SMEM via float4 (r clipped at load) ----
    {
        const float4* xr4 = (const float4*)(xr + base);
        const float4* xi4 = (const float4*)(xi + base);
        const float4* r4  = (const float4*)(r + base);
        #pragma unroll
        for (int rep = 0; rep < 4; rep++) {
            int i = tid + rep * NTHREADS;          // 0..1023
            int m = i >> 7, t4 = (i & 127) << 2;
            float4 a = xr4[i];
            *(float4*)(sxr + m * XS + t4) = a;
            float4 b = xi4[i];
            *(float4*)(sxi + m * XS + t4) = b;
            float4 c = r4[i];
            c.x = fmaxf(c.x, 1e-3f); c.y = fmaxf(c.y, 1e-3f);
            c.z = fmaxf(c.z, 1e-3f); c.w = fmaxf(c.w, 1e-3f);
            *(float4*)(sr + m * XS + t4) = c;
        }
    }
    if (tid < 64) {
        sQ[tid] = make_float2(Qr[(size_t)bf * 64 + tid], Qi[(size_t)bf * 64 + tid]);
    }
    __syncthreads();

    // ---- V accumulation. warp == chunk (64 t's). slot = lane. ----
    ull accx[8], accy[8];
    {
        const int chunk = tid >> 5;
        const int slot  = tid & 31;
        const bool offd = slot < 28;
        int m, n;
        if (offd) { m = c_pm[slot]; n = c_pn[slot]; }
        else      { m = slot - 28;  n = slot - 24; }
        const ulonglong2* pxrm = (const ulonglong2*)(sxr + m * XS + chunk * 64);
        const ulonglong2* pxim = (const ulonglong2*)(sxi + m * XS + chunk * 64);
        const ulonglong2* pxrn = (const ulonglong2*)(sxr + n * XS + chunk * 64);
        const ulonglong2* pxin = (const ulonglong2*)(sxi + n * XS + chunk * 64);
        const float* srl = sr + chunk * 64;

        #pragma unroll
        for (int k = 0; k < 8; k++) { accx[k] = 0ULL; accy[k] = 0ULL; }

        #pragma unroll
        for (int q = 0; q < 16; q++) {            // q indexes groups of 4 t's
            ulonglong2 vrm = pxrm[q];
            ulonglong2 vim = pxim[q];
            ulonglong2 vrn = pxrn[q];
            ulonglong2 vin = pxin[q];
            ull a01, a23, b01, b23;
            if (offd) {
                a01 = f2_fma(vrm.x, vrn.x, f2_mul(vim.x, vin.x));
                a23 = f2_fma(vrm.y, vrn.y, f2_mul(vim.y, vin.y));
                b01 = f2_fma(vim.x, vrn.x, f2_mul(vrm.x ^ SGN2, vin.x));
                b23 = f2_fma(vim.y, vrn.y, f2_mul(vrm.y ^ SGN2, vin.y));
            } else {
                a01 = f2_fma(vrm.x, vrm.x, f2_mul(vim.x, vim.x));
                a23 = f2_fma(vrm.y, vrm.y, f2_mul(vim.y, vim.y));
                b01 = f2_fma(vrn.x, vrn.x, f2_mul(vin.x, vin.x));
                b23 = f2_fma(vrn.y, vrn.y, f2_mul(vin.y, vin.y));
            }
            #pragma unroll
            for (int k = 0; k < 8; k++) {
                ulonglong2 rk = *(const ulonglong2*)(srl + k * XS + q * 4);
                accx[k] = f2_fma(rk.x, a01, accx[k]);
                accx[k] = f2_fma(rk.y, a23, accx[k]);
                accy[k] = f2_fma(rk.x, b01, accy[k]);
                accy[k] = f2_fma(rk.y, b23, accy[k]);
            }
        }
    }
    __syncthreads();   // all sr reads complete before part (aliased) is written

    // write partials: 4x STS.128, conflict-free (slot stride 66 f2 = 528B)
    {
        const int chunk = tid >> 5;
        const int slot  = tid & 31;
        ull* prow = (ull*)(part + slot * PART_SLOT_STRIDE + chunk * 8);
        #pragma unroll
        for (int kp = 0; kp < 4; kp++) {
            float x0l, x0h, y0l, y0h, x1l, x1h, y1l, y1h;
            f2_unpack(accx[2 * kp],     x0l, x0h);
            f2_unpack(accy[2 * kp],     y0l, y0h);
            f2_unpack(accx[2 * kp + 1], x1l, x1h);
            f2_unpack(accy[2 * kp + 1], y1l, y1h);
            ulonglong2 w;
            w.x = f2_pack(x0l + x0h, y0l + y0h);   // float2 for k=2kp
            w.y = f2_pack(x1l + x1h, y1l + y1h);   // float2 for k=2kp+1
            *(ulonglong2*)(prow + 2 * kp) = w;
        }
    }
    __syncthreads();

    // reduce over chunks, fill V. warp = k (tid>>5), lane = slot. 2-way max.
    {
        int slot = tid & 31, k = tid >> 5;
        const float2* prow = part + slot * PART_SLOT_STRIDE + k;
        float2 s = make_float2(0.f, 0.f);
        #pragma unroll
        for (int c = 0; c < 8; c++) {
            float2 p = prow[c * 8];
            s.x += p.x; s.y += p.y;
        }
        s.x *= (1.0f / TDIM);
        s.y *= (1.0f / TDIM);
        if (slot < 28) {
            int m = c_pm[slot], n = c_pn[slot];
            V[(k * 8 + m) * 8 + n] = s;
            V[(k * 8 + n) * 8 + m] = make_float2(s.x, -s.y);
        } else {
            int d = slot - 28;
            V[(k * 8 + d) * 8 + d]           = make_float2(s.x, 0.f);
            V[(k * 8 + d + 4) * 8 + d + 4]   = make_float2(s.y, 0.f);
        }
    }
    __syncthreads();

    // trV + diagonal regularization
    if (tid < 8) {
        int k = tid;
        float tr = 0.f;
        #pragma unroll
        for (int m = 0; m < 8; m++) tr += V[(k * 8 + m) * 8 + m].x;
        float reg = fmaxf(tr, 1.0f) * 1e-6f;
        #pragma unroll
        for (int m = 0; m < 8; m++) V[(k * 8 + m) * 8 + m].x += reg;
    }
    __syncthreads();

    // ---- 2 x 8 sweep, fully register-resident on warp 0 ----
    if (tid < 32) {
        const int lane = tid;
        const int kp = lane >> 2;
        const int j  = lane & 3;
        const int m0 = 2 * j, m1 = 2 * j + 1;

        float2 Vr0[8], Vr1[8];
        #pragma unroll
        for (int n = 0; n < 8; n++) {
            Vr0[n] = V[(kp * 8 + m0) * 8 + n];
            Vr1[n] = V[(kp * 8 + m1) * 8 + n];
        }
        float2 Q0 = sQ[kp * 8 + m0];
        float2 Q1 = sQ[kp * 8 + m1];

        #pragma unroll 1
        for (int it = 0; it < 2; it++) {
            #pragma unroll 1
            for (int k = 0; k < 8; k++) {
                float qr[8], qi[8];
                #pragma unroll
                for (int jp = 0; jp < 4; jp++) {
                    int src = k * 4 + jp;
                    qr[2 * jp]     = __shfl_sync(0xffffffffu, Q0.x, src);
                    qi[2 * jp]     = __shfl_sync(0xffffffffu, Q0.y, src);
                    qr[2 * jp + 1] = __shfl_sync(0xffffffffu, Q1.x, src);
                    qi[2 * jp + 1] = __shfl_sync(0xffffffffu, Q1.y, src);
                }
                float vq0r = 0.f, vq0i = 0.f, vq1r = 0.f, vq1i = 0.f;
                #pragma unroll
                for (int n = 0; n < 8; n++) {
                    vq0r += Vr0[n].x * qr[n] + Vr0[n].y * qi[n];
                    vq0i += Vr0[n].y * qr[n] - Vr0[n].x * qi[n];
                    vq1r += Vr1[n].x * qr[n] + Vr1[n].y * qi[n];
                    vq1i += Vr1[n].y * qr[n] - Vr1[n].x * qi[n];
                }
                float pq  = qr[m0] * vq0r - qi[m0] * vq0i
                          + qr[m1] * vq1r - qi[m1] * vq1i;
                float pnr = Q0.x * vq0r - Q0.y * vq0i
                          + Q1.x * vq1r - Q1.y * vq1i;
                float pni = Q0.x * vq0i + Q0.y * vq0r
                          + Q1.x * vq1i + Q1.y * vq1r;
                pq  += __shfl_xor_sync(0xffffffffu, pq, 1);
                pnr += __shfl_xor_sync(0xffffffffu, pnr, 1);
                pni += __shfl_xor_sync(0xffffffffu, pni, 1);
                pq  += __shfl_xor_sync(0xffffffffu, pq, 2);
                pnr += __shfl_xor_sync(0xffffffffu, pnr, 2);
                pni += __shfl_xor_sync(0xffffffffu, pni, 2);

                float qv = fmaxf(pq, 1e-6f);
                float vrr, vii;
                if (kp == k) {
                    vrr = 1.0f - __frsqrt_rn(qv);
                    vii = 0.0f;
                } else {
                    float inv = __fdividef(1.0f, qv);
                    vrr = pnr * inv;
                    vii = pni * inv;
                }
                Q0.x -= vrr * qr[m0] - vii * qi[m0];
                Q0.y -= vrr * qi[m0] + vii * qr[m0];
                Q1.x -= vrr * qr[m1] - vii * qi[m1];
                Q1.y -= vrr * qi[m1] + vii * qr[m1];
            }
        }
        sQ[kp * 8 + m0] = Q0;
        sQ[kp * 8 + m1] = Q1;
        // packed Q for the Qx phase: sQp[row=kp][col=m] = {(x,x),(y,y)}
        sQp[kp * 8 + m0] = make_ulonglong2(f2_pack(Q0.x, Q0.x), f2_pack(Q0.y, Q0.y));
        sQp[kp * 8 + m1] = make_ulonglong2(f2_pack(Q1.x, Q1.x), f2_pack(Q1.y, Q1.y));
    }
    __syncthreads();

    // ---- Qx = Q @ x ; xt = |Qx|^2. warp = t-chunk, lane = 2 t's; 8 m in regs.
    float local = 0.f;
    float* out_xt = out + QELEMS + base;
    {
        const int chunk = tid >> 5;
        const int lane = tid & 31;
        const int t = chunk * 64 + lane * 2;

        ull arP[8], aiP[8];
        #pragma unroll
        for (int m = 0; m < 8; m++) { arP[m] = 0ULL; aiP[m] = 0ULL; }

        #pragma unroll
        for (int n = 0; n < 8; n++) {
            ull vr  = *(const ull*)(sxr + n * XS + t);
            ull vi  = *(const ull*)(sxi + n * XS + t);
            ull vin = vi ^ SGN2;      // -xi for the ar accumulation
            #pragma unroll
            for (int m = 0; m < 8; m++) {
                ulonglong2 qp = sQp[m * 8 + n];    // broadcast LDS.128 (1 wf)
                arP[m] = f2_fma(qp.x, vr, f2_fma(qp.y, vin, arP[m]));
                aiP[m] = f2_fma(qp.x, vi, f2_fma(qp.y, vr,  aiP[m]));
            }
        }
        #pragma unroll
        for (int m = 0; m < 8; m++) {
            float r0, r1, i0, i1;
            f2_unpack(arP[m], r0, r1);
            f2_unpack(aiP[m], i0, i1);
            float v0 = r0 * r0 + i0 * i0;
            float v1 = r1 * r1 + i1 * i1;
            local += v0 + v1;
            *(float2*)(out_xt + m * TDIM + t) = make_float2(v0, v1);
        }
    }
    // write unnormalized Q (real part only — output buffer is float32)
    if (tid < 64) {
        out[(size_t)bf * 64 + tid] = sQ[tid].x;
    }
    // deterministic block reduction: warp shfl tree -> 8 partials -> warp 0
    {
        #pragma unroll
        for (int d = 16; d > 0; d >>= 1)
            local += __shfl_xor_sync(0xffffffffu, local, d);
        if ((tid & 31) == 0) red[tid >> 5] = local;
    }
    __syncthreads();
    if (tid < 32) {
        float s = (tid < 8) ? red[tid] : 0.f;
        #pragma unroll
        for (int d = 4; d > 0; d >>= 1)
            s += __shfl_xor_sync(0xffffffffu, s, d);
        if (tid == 0) g_partial[bf] = s;
    }
}

__global__ void iss_reduce()
{
    __shared__ float red[256];
    int b = blockIdx.x, tid = threadIdx.x;
    float s = 0.f;
    for (int i = tid; i < FDIM; i += 256) s += g_partial[b * FDIM + i];
    red[tid] = s;
    __syncthreads();
    for (int st = 128; st > 0; st >>= 1) {
        if (tid < st) red[tid] += red[tid + st];
        __syncthreads();
    }
    if (tid == 0) {
        float scale = red[0] / (float)PER_B_XT;
        g_xtscale[b] = 1.0f / scale;
        g_qscale[b]  = 1.0f / sqrtf(fmaxf(scale, 1e-6f));
    }
}

// single normalization pass over the whole output buffer (float4)
__global__ void iss_norm(float4* __restrict__ outv)
{
    size_t idx = (size_t)blockIdx.x * blockDim.x + threadIdx.x;
    if (idx >= (size_t)TOTAL4) return;
    float s;
    if (idx < (size_t)Q4) {
        s = g_qscale[(int)(idx / (PER_B_QE / 4))];
    } else {
        s = g_xtscale[(int)((idx - Q4) / (PER_B_XT / 4))];
    }
    float4 v = outv[idx];
    v.x *= s; v.y *= s; v.z *= s; v.w *= s;
    outv[idx] = v;
}

extern "C" void kernel_launch(void* const* d_in, const int* in_sizes, int n_in,
                              void* d_out, int out_size)
{
    const float* r  = (const float*)d_in[0];
    const float* Qr = (const float*)d_in[1];
    const float* Qi = (const float*)d_in[2];
    const float* xr = (const float*)d_in[3];
    const float* xi = (const float*)d_in[4];
    float* out = (float*)d_out;

    cudaFuncSetAttribute(iss_main, cudaFuncAttributeMaxDynamicSharedMemorySize, SMEM_BYTES);

    iss_main<<<NBF, NTHREADS, SMEM_BYTES>>>(r, Qr, Qi, xr, xi, out);
    iss_reduce<<<BDIM, 256>>>();
    iss_norm<<<(TOTAL4 + 255) / 256, 256>>>((float4*)out);
}